// round 4
// baseline (speedup 1.0000x reference)
#include <cuda_runtime.h>
#include <math.h>

#define NNODE 50000
#define NEDGE 500000
#define SDIM 128
#define VDIM 3
#define HID 64
#define NLAYER 4
#define M3DIM 134     // SD + 2*VD
#define K1DIM 257     // 2*SD + 1
#define TEB 128       // edges per block
#define NTH 256

// -------- scratch (no cudaMalloc allowed) --------
__device__ float g_sagg[NNODE * SDIM];
__device__ float g_vagg[NNODE * VDIM * 3];
__device__ float g_cnt[NNODE];
__device__ float g_C[NEDGE];

__device__ __forceinline__ float silu(float x) {
    return x / (1.0f + __expf(-x));
}

// -------- per-edge envelope C and in-degree counts --------
__global__ void init_kernel(const int* __restrict__ ei, const float* __restrict__ dvec) {
    int e = blockIdx.x * blockDim.x + threadIdx.x;
    if (e < NEDGE) {
        float dv = dvec[e];
        float C = 0.5f * (cosf(0.62831853071795864769f * dv) + 1.0f); // pi/5
        if (!(dv < 5.0f)) C = 0.0f;
        g_C[e] = C;
        atomicAdd(&g_cnt[ei[e]], 1.0f);   // dst = edge_index[0]
    }
}

// -------- fused edge kernel: gather -> MLP(257->64->64->134) -> scatter --------
// smem float offsets
#define EO_W1 0                 // 257*64 = 16448
#define EO_W2 16448             // 64*64  = 4096
#define EO_W3 20544             // 64*136 = 8704 (padded stride 136)
#define EO_H1 29248             // 128*68 = 8704
#define EO_H2 37952             // 128*68 = 8704
#define EO_X  46656             // 16*128 = 2048
#define EO_IDST 48704           // 128 ints
#define EO_ISRC 48832           // 128 ints
#define EO_C  48960             // 128
#define EO_D  49088             // 128
#define EDGE_SMEM_FLOATS 49216  // 196864 bytes

__global__ void __launch_bounds__(NTH, 1) edge_kernel(
    const float* __restrict__ s, const float* __restrict__ v,
    const int* __restrict__ ei, const float* __restrict__ dvec,
    const float* __restrict__ r,
    const float* __restrict__ W1, const float* __restrict__ b1,
    const float* __restrict__ W2, const float* __restrict__ b2,
    const float* __restrict__ W3, const float* __restrict__ b3)
{
    extern __shared__ float sm[];
    float* Ws1 = sm + EO_W1;
    float* Ws2 = sm + EO_W2;
    float* Ws3 = sm + EO_W3;
    float* Hs1 = sm + EO_H1;
    float* Hs2 = sm + EO_H2;
    float* Xs  = sm + EO_X;
    int*   sdst = (int*)(sm + EO_IDST);
    int*   ssrc = (int*)(sm + EO_ISRC);
    float* sC   = sm + EO_C;
    float* sd   = sm + EO_D;

    const int tid = threadIdx.x;
    const int e0  = blockIdx.x * TEB;

    // stage weights (L2 -> smem, once per block)
    for (int i = tid; i < K1DIM * HID; i += NTH) Ws1[i] = W1[i];
    for (int i = tid; i < HID * HID;  i += NTH) Ws2[i] = W2[i];
    for (int i = tid; i < HID * M3DIM; i += NTH)
        Ws3[(i / M3DIM) * 136 + (i % M3DIM)] = W3[i];
    // stage edge metadata
    if (tid < TEB) {
        int e  = e0 + tid;
        int ec = (e < NEDGE) ? e : 0;
        sdst[tid] = ei[ec];
        ssrc[tid] = ei[NEDGE + ec];
        sC[tid]   = (e < NEDGE) ? g_C[ec] : 0.0f;
        sd[tid]   = dvec[ec];
    }
    __syncthreads();

    const int jt = tid & 15;       // 16 j-groups
    const int et = tid >> 4;       // 16 edge-groups
    const int j0 = jt * 4;
    const int eb = et * 8;

    // X staging mapping: thread -> (edge, k-offset)
    const int xe = tid & 127;
    const int xk = (tid >> 7) * 8;
    const long xdst = sdst[xe];
    const long xsrc = ssrc[xe];

    // ---------- GEMM1: X(128x257) @ W1(257x64) ----------
    float acc[8][4];
#pragma unroll
    for (int i = 0; i < 8; i++)
#pragma unroll
        for (int u = 0; u < 4; u++) acc[i][u] = 0.0f;

    for (int kc = 0; kc < 16; kc++) {     // k = 0..255 in 16-wide chunks
        int kg = kc * 16 + xk;
        const float* rowp = (kg < SDIM) ? (s + xdst * SDIM + kg)
                                        : (s + xsrc * SDIM + (kg - SDIM));
        float4 q0 = *(const float4*)rowp;
        float4 q1 = *(const float4*)(rowp + 4);
        __syncthreads();
        Xs[(xk + 0) * TEB + xe] = q0.x;
        Xs[(xk + 1) * TEB + xe] = q0.y;
        Xs[(xk + 2) * TEB + xe] = q0.z;
        Xs[(xk + 3) * TEB + xe] = q0.w;
        Xs[(xk + 4) * TEB + xe] = q1.x;
        Xs[(xk + 5) * TEB + xe] = q1.y;
        Xs[(xk + 6) * TEB + xe] = q1.z;
        Xs[(xk + 7) * TEB + xe] = q1.w;
        __syncthreads();
#pragma unroll
        for (int kk = 0; kk < 16; kk++) {
            float4 bv = *(const float4*)&Ws1[(kc * 16 + kk) * HID + j0];
            float4 a0 = *(const float4*)&Xs[kk * TEB + eb];
            float4 a1 = *(const float4*)&Xs[kk * TEB + eb + 4];
            float av[8] = {a0.x, a0.y, a0.z, a0.w, a1.x, a1.y, a1.z, a1.w};
            float bw[4] = {bv.x, bv.y, bv.z, bv.w};
#pragma unroll
            for (int i = 0; i < 8; i++)
#pragma unroll
                for (int u = 0; u < 4; u++)
                    acc[i][u] = fmaf(av[i], bw[u], acc[i][u]);
        }
    }
    // epilogue: + d*W1[256] + b1, silu
    {
        float wlast[4], bb[4];
#pragma unroll
        for (int u = 0; u < 4; u++) { wlast[u] = Ws1[256 * HID + j0 + u]; bb[u] = b1[j0 + u]; }
#pragma unroll
        for (int i = 0; i < 8; i++) {
            float dd = sd[eb + i];
#pragma unroll
            for (int u = 0; u < 4; u++) {
                float x = acc[i][u] + dd * wlast[u] + bb[u];
                Hs1[(eb + i) * 68 + j0 + u] = silu(x);
            }
        }
    }
    __syncthreads();

    // ---------- GEMM2: H1(128x64) @ W2(64x64) ----------
    float acc2[8][4];
#pragma unroll
    for (int i = 0; i < 8; i++)
#pragma unroll
        for (int u = 0; u < 4; u++) acc2[i][u] = 0.0f;
#pragma unroll 8
    for (int k = 0; k < HID; k++) {
        float4 bv = *(const float4*)&Ws2[k * HID + j0];
        float bw[4] = {bv.x, bv.y, bv.z, bv.w};
#pragma unroll
        for (int i = 0; i < 8; i++) {
            float a = Hs1[(eb + i) * 68 + k];
#pragma unroll
            for (int u = 0; u < 4; u++)
                acc2[i][u] = fmaf(a, bw[u], acc2[i][u]);
        }
    }
    {
        float bb[4];
#pragma unroll
        for (int u = 0; u < 4; u++) bb[u] = b2[j0 + u];
#pragma unroll
        for (int i = 0; i < 8; i++)
#pragma unroll
            for (int u = 0; u < 4; u++)
                Hs2[(eb + i) * 68 + j0 + u] = silu(acc2[i][u] + bb[u]);
    }
    __syncthreads();

    // ---------- GEMM3: H2(128x64) @ W3(64x134) ----------
    const int j3 = jt * 8;      // first 128 cols (ms)
    float acc3[8][8];
#pragma unroll
    for (int i = 0; i < 8; i++)
#pragma unroll
        for (int u = 0; u < 8; u++) acc3[i][u] = 0.0f;
#pragma unroll 4
    for (int k = 0; k < HID; k++) {
        float4 b0 = *(const float4*)&Ws3[k * 136 + j3];
        float4 b1v = *(const float4*)&Ws3[k * 136 + j3 + 4];
        float bw[8] = {b0.x, b0.y, b0.z, b0.w, b1v.x, b1v.y, b1v.z, b1v.w};
#pragma unroll
        for (int i = 0; i < 8; i++) {
            float a = Hs2[(eb + i) * 68 + k];
#pragma unroll
            for (int u = 0; u < 8; u++)
                acc3[i][u] = fmaf(a, bw[u], acc3[i][u]);
        }
    }
    // scatter ms * C into s_agg
    {
        float bb3[8];
#pragma unroll
        for (int u = 0; u < 8; u++) bb3[u] = b3[j3 + u];
#pragma unroll
        for (int i = 0; i < 8; i++) {
            int e = e0 + eb + i;
            if (e < NEDGE) {
                float Cv = sC[eb + i];
                float* sa = g_sagg + (long)sdst[eb + i] * SDIM + j3;
#pragma unroll
                for (int u = 0; u < 8; u++)
                    atomicAdd(&sa[u], (acc3[i][u] + bb3[u]) * Cv);
            }
        }
    }
    // gv/gr (cols 128..133) + vector message scatter
    if (tid < TEB) {
        int e = e0 + tid;
        if (e < NEDGE) {
            float g6[6];
#pragma unroll
            for (int u = 0; u < 6; u++) {
                float a = b3[128 + u];
#pragma unroll 8
                for (int k = 0; k < HID; k++)
                    a = fmaf(Hs2[tid * 68 + k], Ws3[k * 136 + 128 + u], a);
                g6[u] = a;
            }
            float Cv = sC[tid];
            long srcn = ssrc[tid];
            long dstn = sdst[tid];
            float r0 = r[(long)e * 3 + 0];
            float r1 = r[(long)e * 3 + 1];
            float r2 = r[(long)e * 3 + 2];
            const float* vs = v + srcn * 9;
            float* va = g_vagg + dstn * 9;
#pragma unroll
            for (int i = 0; i < 3; i++) {
                float gvi = g6[i], gri = g6[3 + i];
                atomicAdd(&va[i * 3 + 0], (vs[i * 3 + 0] * gvi + r0 * gri) * Cv);
                atomicAdd(&va[i * 3 + 1], (vs[i * 3 + 1] * gvi + r1 * gri) * Cv);
                atomicAdd(&va[i * 3 + 2], (vs[i * 3 + 2] * gvi + r2 * gri) * Cv);
            }
        }
    }
}

// -------- fused node kernel: [s|s_agg] -> MLP(256->64->128), s += ..., v += v_agg/cnt --------
#define NO_W1 0                 // 256*64 = 16384
#define NO_W2 16384             // 64*128 = 8192
#define NO_U  24576             // 128*68 = 8704
#define NO_X  33280             // 16*128 = 2048
#define NODE_SMEM_FLOATS 35328  // 141312 bytes

__global__ void __launch_bounds__(NTH, 1) node_kernel(
    float* __restrict__ s, float* __restrict__ v,
    const float* __restrict__ Wn1, const float* __restrict__ bn1,
    const float* __restrict__ Wn2, const float* __restrict__ bn2)
{
    extern __shared__ float sm[];
    float* Ws1 = sm + NO_W1;
    float* Ws2 = sm + NO_W2;
    float* Us  = sm + NO_U;
    float* Xs  = sm + NO_X;

    const int tid = threadIdx.x;
    const int n0  = blockIdx.x * 128;

    for (int i = tid; i < 2 * SDIM * HID; i += NTH) Ws1[i] = Wn1[i];
    for (int i = tid; i < HID * SDIM;    i += NTH) Ws2[i] = Wn2[i];

    const int jt = tid & 15, et = tid >> 4;
    const int j0 = jt * 4,  nb = et * 8;
    const int xn = tid & 127;
    const int xk = (tid >> 7) * 8;
    int xcl = n0 + xn; if (xcl > NNODE - 1) xcl = NNODE - 1;
    const long xrow = (long)xcl;

    float acc[8][4];
#pragma unroll
    for (int i = 0; i < 8; i++)
#pragma unroll
        for (int u = 0; u < 4; u++) acc[i][u] = 0.0f;

    for (int kc = 0; kc < 16; kc++) {
        int kg = kc * 16 + xk;
        const float* rowp = (kg < SDIM) ? (s + xrow * SDIM + kg)
                                        : (g_sagg + xrow * SDIM + (kg - SDIM));
        float4 q0 = *(const float4*)rowp;
        float4 q1 = *(const float4*)(rowp + 4);
        __syncthreads();
        Xs[(xk + 0) * 128 + xn] = q0.x;
        Xs[(xk + 1) * 128 + xn] = q0.y;
        Xs[(xk + 2) * 128 + xn] = q0.z;
        Xs[(xk + 3) * 128 + xn] = q0.w;
        Xs[(xk + 4) * 128 + xn] = q1.x;
        Xs[(xk + 5) * 128 + xn] = q1.y;
        Xs[(xk + 6) * 128 + xn] = q1.z;
        Xs[(xk + 7) * 128 + xn] = q1.w;
        __syncthreads();
#pragma unroll
        for (int kk = 0; kk < 16; kk++) {
            float4 bv = *(const float4*)&Ws1[(kc * 16 + kk) * HID + j0];
            float4 a0 = *(const float4*)&Xs[kk * 128 + nb];
            float4 a1 = *(const float4*)&Xs[kk * 128 + nb + 4];
            float av[8] = {a0.x, a0.y, a0.z, a0.w, a1.x, a1.y, a1.z, a1.w};
            float bw[4] = {bv.x, bv.y, bv.z, bv.w};
#pragma unroll
            for (int i = 0; i < 8; i++)
#pragma unroll
                for (int u = 0; u < 4; u++)
                    acc[i][u] = fmaf(av[i], bw[u], acc[i][u]);
        }
    }
    {
        float bb[4];
#pragma unroll
        for (int u = 0; u < 4; u++) bb[u] = bn1[j0 + u];
#pragma unroll
        for (int i = 0; i < 8; i++)
#pragma unroll
            for (int u = 0; u < 4; u++)
                Us[(nb + i) * 68 + j0 + u] = silu(acc[i][u] + bb[u]);
    }
    __syncthreads();

    // GEMM-n2: U(128x64) @ Wn2(64x128), s += out + bn2
    const int j3 = jt * 8;
    float acc3[8][8];
#pragma unroll
    for (int i = 0; i < 8; i++)
#pragma unroll
        for (int u = 0; u < 8; u++) acc3[i][u] = 0.0f;
#pragma unroll 4
    for (int k = 0; k < HID; k++) {
        float4 b0 = *(const float4*)&Ws2[k * SDIM + j3];
        float4 b1v = *(const float4*)&Ws2[k * SDIM + j3 + 4];
        float bw[8] = {b0.x, b0.y, b0.z, b0.w, b1v.x, b1v.y, b1v.z, b1v.w};
#pragma unroll
        for (int i = 0; i < 8; i++) {
            float a = Us[(nb + i) * 68 + k];
#pragma unroll
            for (int u = 0; u < 8; u++)
                acc3[i][u] = fmaf(a, bw[u], acc3[i][u]);
        }
    }
    {
        float bb2[8];
#pragma unroll
        for (int u = 0; u < 8; u++) bb2[u] = bn2[j3 + u];
#pragma unroll
        for (int i = 0; i < 8; i++) {
            int n = n0 + nb + i;
            if (n < NNODE) {
                float* sp = s + (long)n * SDIM + j3;
#pragma unroll
                for (int u = 0; u < 8; u++)
                    sp[u] += acc3[i][u] + bb2[u];
            }
        }
    }
    // v += v_agg * inv_cnt
    if (tid < 128) {
        int n = n0 + tid;
        if (n < NNODE) {
            float ic = 1.0f / fmaxf(g_cnt[n], 1.0f);
            float* vp = v + (long)n * 9;
            const float* vap = g_vagg + (long)n * 9;
#pragma unroll
            for (int q = 0; q < 9; q++)
                vp[q] += vap[q] * ic;
        }
    }
}

// -------- launch --------
extern "C" void kernel_launch(void* const* d_in, const int* in_sizes, int n_in,
                              void* d_out, int out_size)
{
    const float* s_in = (const float*)d_in[0];
    const float* v_in = (const float*)d_in[1];
    const int*   ei   = (const int*)d_in[2];
    const float* dvec = (const float*)d_in[3];
    const float* r    = (const float*)d_in[4];
    const float* W1   = (const float*)d_in[5];
    const float* b1   = (const float*)d_in[6];
    const float* W2   = (const float*)d_in[7];
    const float* b2   = (const float*)d_in[8];
    const float* W3   = (const float*)d_in[9];
    const float* b3   = (const float*)d_in[10];
    const float* Wn1  = (const float*)d_in[11];
    const float* bn1  = (const float*)d_in[12];
    const float* Wn2  = (const float*)d_in[13];
    const float* bn2  = (const float*)d_in[14];

    float* s = (float*)d_out;
    float* v = s + (size_t)NNODE * SDIM;

    cudaFuncSetAttribute(edge_kernel, cudaFuncAttributeMaxDynamicSharedMemorySize,
                         EDGE_SMEM_FLOATS * 4);
    cudaFuncSetAttribute(node_kernel, cudaFuncAttributeMaxDynamicSharedMemorySize,
                         NODE_SMEM_FLOATS * 4);

    void *p_cnt, *p_sagg, *p_vagg;
    cudaGetSymbolAddress(&p_cnt, g_cnt);
    cudaGetSymbolAddress(&p_sagg, g_sagg);
    cudaGetSymbolAddress(&p_vagg, g_vagg);

    cudaMemcpyAsync(s, s_in, sizeof(float) * NNODE * SDIM, cudaMemcpyDeviceToDevice, 0);
    cudaMemcpyAsync(v, v_in, sizeof(float) * NNODE * 9, cudaMemcpyDeviceToDevice, 0);
    cudaMemsetAsync(p_cnt, 0, sizeof(float) * NNODE, 0);
    init_kernel<<<(NEDGE + 255) / 256, 256>>>(ei, dvec);

    for (int l = 0; l < NLAYER; l++) {
        cudaMemsetAsync(p_sagg, 0, sizeof(float) * NNODE * SDIM, 0);
        cudaMemsetAsync(p_vagg, 0, sizeof(float) * NNODE * 9, 0);
        edge_kernel<<<(NEDGE + TEB - 1) / TEB, NTH, EDGE_SMEM_FLOATS * 4>>>(
            s, v, ei, dvec, r,
            W1 + (size_t)l * K1DIM * HID, b1 + (size_t)l * HID,
            W2 + (size_t)l * HID * HID,   b2 + (size_t)l * HID,
            W3 + (size_t)l * HID * M3DIM, b3 + (size_t)l * M3DIM);
        node_kernel<<<(NNODE + 127) / 128, NTH, NODE_SMEM_FLOATS * 4>>>(
            s, v,
            Wn1 + (size_t)l * 2 * SDIM * HID, bn1 + (size_t)l * HID,
            Wn2 + (size_t)l * HID * SDIM,     bn2 + (size_t)l * SDIM);
    }
}

// round 5
// speedup vs baseline: 1.0690x; 1.0690x over previous
#include <cuda_runtime.h>
#include <math.h>

#define NNODE 50000
#define NEDGE 500000
#define SDIM 128
#define VDIM 3
#define HID 64
#define NLAYER 4
#define M3DIM 134     // SD + 2*VD
#define K1DIM 257     // 2*SD + 1
#define TEB 128       // edges per block
#define NTH 256

typedef unsigned long long u64;

// -------- scratch (no cudaMalloc allowed) --------
__device__ float g_sagg[NNODE * SDIM];
__device__ float g_vagg[NNODE * VDIM * 3];
__device__ float g_cnt[NNODE];

__device__ __forceinline__ float silu(float x) {
    return x / (1.0f + __expf(-x));
}
// packed f32x2 helpers
__device__ __forceinline__ u64 pack2(float x) {
    u64 r; asm("mov.b64 %0, {%1, %1};" : "=l"(r) : "f"(x)); return r;
}
__device__ __forceinline__ void fma2(u64& d, u64 a, u64 b) {
    asm("fma.rn.f32x2 %0, %1, %2, %0;" : "+l"(d) : "l"(a), "l"(b));
}
__device__ __forceinline__ float2 u2f(u64 x) {
    float2 f; asm("mov.b64 {%0, %1}, %2;" : "=f"(f.x), "=f"(f.y) : "l"(x)); return f;
}

// -------- in-degree counts --------
__global__ void init_kernel(const int* __restrict__ ei) {
    int e = blockIdx.x * blockDim.x + threadIdx.x;
    if (e < NEDGE) atomicAdd(&g_cnt[ei[e]], 1.0f);
}

// -------- fused edge kernel: gather -> MLP(257->64->64->134) -> scatter --------
#define EO_W1 0                 // 257*64 = 16448
#define EO_W2 16448             // 64*64  = 4096
#define EO_W3 20544             // 64*136 = 8704 (padded stride 136)
#define EO_H1 29248             // 128*68 = 8704
#define EO_H2 37952             // 128*68 = 8704
#define EO_X  46656             // 16*128 = 2048 (also reused as gv/gr staging)
#define EO_IDST 48704           // 128 ints
#define EO_ISRC 48832           // 128 ints
#define EO_C  48960             // 128
#define EO_D  49088             // 128
#define EDGE_SMEM_FLOATS 49216  // 196864 bytes

__global__ void __launch_bounds__(NTH, 1) edge_kernel(
    const float* __restrict__ s, const float* __restrict__ v,
    const int* __restrict__ ei, const float* __restrict__ dvec,
    const float* __restrict__ r,
    const float* __restrict__ W1, const float* __restrict__ b1,
    const float* __restrict__ W2, const float* __restrict__ b2,
    const float* __restrict__ W3, const float* __restrict__ b3)
{
    extern __shared__ float sm[];
    float* Ws1 = sm + EO_W1;
    float* Ws2 = sm + EO_W2;
    float* Ws3 = sm + EO_W3;
    float* Hs1 = sm + EO_H1;
    float* Hs2 = sm + EO_H2;
    float* Xs  = sm + EO_X;
    int*   sdst = (int*)(sm + EO_IDST);
    int*   ssrc = (int*)(sm + EO_ISRC);
    float* sC   = sm + EO_C;
    float* sd   = sm + EO_D;

    const int tid = threadIdx.x;
    const int e0  = blockIdx.x * TEB;

    // stage weights
    for (int i = tid; i < K1DIM * HID; i += NTH) Ws1[i] = W1[i];
    for (int i = tid; i < HID * HID;  i += NTH) Ws2[i] = W2[i];
    for (int i = tid; i < HID * M3DIM; i += NTH)
        Ws3[(i / M3DIM) * 136 + (i % M3DIM)] = W3[i];
    // stage edge metadata (C computed inline)
    if (tid < TEB) {
        int e  = e0 + tid;
        int ec = (e < NEDGE) ? e : 0;
        sdst[tid] = ei[ec];
        ssrc[tid] = ei[NEDGE + ec];
        float dv = dvec[ec];
        float C = 0.5f * (cosf(0.62831853071795864769f * dv) + 1.0f);
        if (!(dv < 5.0f)) C = 0.0f;
        sC[tid] = (e < NEDGE) ? C : 0.0f;
        sd[tid] = dv;
    }
    __syncthreads();

    const int jt = tid & 15;       // 16 j-groups
    const int et = tid >> 4;       // 16 edge-groups
    const int j0 = jt * 4;
    const int eb = et * 8;

    // X staging mapping: thread -> (edge, k-offset)
    const int xe = tid & 127;
    const int xk = (tid >> 7) * 8;
    const long xdst = sdst[xe];
    const long xsrc = ssrc[xe];

    // ---------- GEMM1: X(128x257) @ W1(257x64), f32x2 packed along edges ----------
    u64 accp[4][4];
#pragma unroll
    for (int i = 0; i < 4; i++)
#pragma unroll
        for (int u = 0; u < 4; u++) accp[i][u] = 0ull;

    float4 q0, q1, p0, p1;
    {
        const float* rowp = (xk < SDIM) ? (s + xdst * SDIM + xk)
                                        : (s + xsrc * SDIM + (xk - SDIM));
        q0 = *(const float4*)rowp;
        q1 = *(const float4*)(rowp + 4);
    }
    for (int kc = 0; kc < 16; kc++) {
        __syncthreads();
        Xs[(xk + 0) * TEB + xe] = q0.x;
        Xs[(xk + 1) * TEB + xe] = q0.y;
        Xs[(xk + 2) * TEB + xe] = q0.z;
        Xs[(xk + 3) * TEB + xe] = q0.w;
        Xs[(xk + 4) * TEB + xe] = q1.x;
        Xs[(xk + 5) * TEB + xe] = q1.y;
        Xs[(xk + 6) * TEB + xe] = q1.z;
        Xs[(xk + 7) * TEB + xe] = q1.w;
        if (kc < 15) {   // prefetch next chunk into registers (hidden under compute)
            int kg = (kc + 1) * 16 + xk;
            const float* rowp = (kg < SDIM) ? (s + xdst * SDIM + kg)
                                            : (s + xsrc * SDIM + (kg - SDIM));
            p0 = *(const float4*)rowp;
            p1 = *(const float4*)(rowp + 4);
        }
        __syncthreads();
#pragma unroll
        for (int kk = 0; kk < 16; kk++) {
            float4 bv = *(const float4*)&Ws1[(kc * 16 + kk) * HID + j0];
            u64 bp0 = pack2(bv.x), bp1 = pack2(bv.y), bp2 = pack2(bv.z), bp3 = pack2(bv.w);
            ulonglong2 A0 = *(const ulonglong2*)&Xs[kk * TEB + eb];
            ulonglong2 A1 = *(const ulonglong2*)&Xs[kk * TEB + eb + 4];
            u64 ap[4] = {A0.x, A0.y, A1.x, A1.y};
#pragma unroll
            for (int ip = 0; ip < 4; ip++) {
                fma2(accp[ip][0], ap[ip], bp0);
                fma2(accp[ip][1], ap[ip], bp1);
                fma2(accp[ip][2], ap[ip], bp2);
                fma2(accp[ip][3], ap[ip], bp3);
            }
        }
        q0 = p0; q1 = p1;
    }
    // epilogue: + d*W1[256] + b1, silu, vectorized store
    {
        float wlast[4], bb[4];
#pragma unroll
        for (int u = 0; u < 4; u++) { wlast[u] = Ws1[256 * HID + j0 + u]; bb[u] = b1[j0 + u]; }
#pragma unroll
        for (int ip = 0; ip < 4; ip++) {
            float2 f[4];
#pragma unroll
            for (int u = 0; u < 4; u++) f[u] = u2f(accp[ip][u]);
            float dd0 = sd[eb + 2 * ip], dd1 = sd[eb + 2 * ip + 1];
            float4 o0, o1;
            o0.x = silu(f[0].x + dd0 * wlast[0] + bb[0]);
            o0.y = silu(f[1].x + dd0 * wlast[1] + bb[1]);
            o0.z = silu(f[2].x + dd0 * wlast[2] + bb[2]);
            o0.w = silu(f[3].x + dd0 * wlast[3] + bb[3]);
            o1.x = silu(f[0].y + dd1 * wlast[0] + bb[0]);
            o1.y = silu(f[1].y + dd1 * wlast[1] + bb[1]);
            o1.z = silu(f[2].y + dd1 * wlast[2] + bb[2]);
            o1.w = silu(f[3].y + dd1 * wlast[3] + bb[3]);
            *(float4*)&Hs1[(eb + 2 * ip) * 68 + j0]     = o0;
            *(float4*)&Hs1[(eb + 2 * ip + 1) * 68 + j0] = o1;
        }
    }
    __syncthreads();

    // ---------- GEMM2: H1(128x64) @ W2(64x64), f32x2 packed along columns ----------
    u64 acc2p[8][2];
#pragma unroll
    for (int i = 0; i < 8; i++) { acc2p[i][0] = 0ull; acc2p[i][1] = 0ull; }
#pragma unroll 4
    for (int k = 0; k < HID; k++) {
        ulonglong2 bvp = *(const ulonglong2*)&Ws2[k * HID + j0];
#pragma unroll
        for (int i = 0; i < 8; i++) {
            u64 ap = pack2(Hs1[(eb + i) * 68 + k]);
            fma2(acc2p[i][0], ap, bvp.x);
            fma2(acc2p[i][1], ap, bvp.y);
        }
    }
    {
        float bb[4];
#pragma unroll
        for (int u = 0; u < 4; u++) bb[u] = b2[j0 + u];
#pragma unroll
        for (int i = 0; i < 8; i++) {
            float2 f0 = u2f(acc2p[i][0]), f1 = u2f(acc2p[i][1]);
            float4 o;
            o.x = silu(f0.x + bb[0]);
            o.y = silu(f0.y + bb[1]);
            o.z = silu(f1.x + bb[2]);
            o.w = silu(f1.y + bb[3]);
            *(float4*)&Hs2[(eb + i) * 68 + j0] = o;
        }
    }
    __syncthreads();

    // ---------- GEMM3: H2(128x64) @ W3(64x134), f32x2 packed along columns ----------
    const int j3 = jt * 8;      // first 128 cols (ms)
    u64 acc3p[8][4];
#pragma unroll
    for (int i = 0; i < 8; i++)
#pragma unroll
        for (int u = 0; u < 4; u++) acc3p[i][u] = 0ull;
#pragma unroll 2
    for (int k = 0; k < HID; k++) {
        ulonglong2 B0 = *(const ulonglong2*)&Ws3[k * 136 + j3];
        ulonglong2 B1 = *(const ulonglong2*)&Ws3[k * 136 + j3 + 4];
        u64 bp[4] = {B0.x, B0.y, B1.x, B1.y};
#pragma unroll
        for (int i = 0; i < 8; i++) {
            u64 ap = pack2(Hs2[(eb + i) * 68 + k]);
            fma2(acc3p[i][0], ap, bp[0]);
            fma2(acc3p[i][1], ap, bp[1]);
            fma2(acc3p[i][2], ap, bp[2]);
            fma2(acc3p[i][3], ap, bp[3]);
        }
    }
    // scatter ms * C into s_agg
    {
        float bb3[8];
#pragma unroll
        for (int u = 0; u < 8; u++) bb3[u] = b3[j3 + u];
#pragma unroll
        for (int i = 0; i < 8; i++) {
            int e = e0 + eb + i;
            if (e < NEDGE) {
                float Cv = sC[eb + i];
                float* sa = g_sagg + (long)sdst[eb + i] * SDIM + j3;
#pragma unroll
                for (int u = 0; u < 4; u++) {
                    float2 f = u2f(acc3p[i][u]);
                    atomicAdd(&sa[2 * u],     (f.x + bb3[2 * u])     * Cv);
                    atomicAdd(&sa[2 * u + 1], (f.y + bb3[2 * u + 1]) * Cv);
                }
            }
        }
    }

    // ---- gv/gr (cols 128..133): all 256 threads compute, 128 scatter ----
    {
        float* sG = Xs;   // reuse (768 floats needed, 2048 available)
        const int te = tid & 127;
        const int th = tid >> 7;     // 0 -> gv, 1 -> gr
#pragma unroll
        for (int u = 0; u < 3; u++) {
            int col = 128 + th * 3 + u;
            float a = b3[col];
#pragma unroll 8
            for (int k = 0; k < HID; k++)
                a = fmaf(Hs2[te * 68 + k], Ws3[k * 136 + col], a);
            sG[te * 6 + th * 3 + u] = a;
        }
        __syncthreads();
        if (tid < TEB) {
            int e = e0 + tid;
            if (e < NEDGE) {
                float Cv = sC[tid];
                long srcn = ssrc[tid];
                long dstn = sdst[tid];
                float r0 = r[(long)e * 3 + 0];
                float r1 = r[(long)e * 3 + 1];
                float r2 = r[(long)e * 3 + 2];
                const float* vs = v + srcn * 9;
                float* va = g_vagg + dstn * 9;
#pragma unroll
                for (int i = 0; i < 3; i++) {
                    float gvi = sG[tid * 6 + i], gri = sG[tid * 6 + 3 + i];
                    atomicAdd(&va[i * 3 + 0], (vs[i * 3 + 0] * gvi + r0 * gri) * Cv);
                    atomicAdd(&va[i * 3 + 1], (vs[i * 3 + 1] * gvi + r1 * gri) * Cv);
                    atomicAdd(&va[i * 3 + 2], (vs[i * 3 + 2] * gvi + r2 * gri) * Cv);
                }
            }
        }
    }
}

// -------- fused node kernel: [s|s_agg] -> MLP(256->64->128), s += ..., v += v_agg/cnt --------
#define NO_W1 0                 // 256*64 = 16384
#define NO_W2 16384             // 64*128 = 8192
#define NO_U  24576             // 128*68 = 8704
#define NO_X  33280             // 16*128 = 2048
#define NODE_SMEM_FLOATS 35328  // 141312 bytes

__global__ void __launch_bounds__(NTH, 1) node_kernel(
    float* __restrict__ s, float* __restrict__ v,
    const float* __restrict__ Wn1, const float* __restrict__ bn1,
    const float* __restrict__ Wn2, const float* __restrict__ bn2)
{
    extern __shared__ float sm[];
    float* Ws1 = sm + NO_W1;
    float* Ws2 = sm + NO_W2;
    float* Us  = sm + NO_U;
    float* Xs  = sm + NO_X;

    const int tid = threadIdx.x;
    const int n0  = blockIdx.x * 128;

    for (int i = tid; i < 2 * SDIM * HID; i += NTH) Ws1[i] = Wn1[i];
    for (int i = tid; i < HID * SDIM;    i += NTH) Ws2[i] = Wn2[i];

    const int jt = tid & 15, et = tid >> 4;
    const int j0 = jt * 4,  nb = et * 8;
    const int xn = tid & 127;
    const int xk = (tid >> 7) * 8;
    int xcl = n0 + xn; if (xcl > NNODE - 1) xcl = NNODE - 1;
    const long xrow = (long)xcl;

    // ---------- GEMM-n1: [s|s_agg](128x256) @ Wn1(256x64), i-packed ----------
    u64 accp[4][4];
#pragma unroll
    for (int i = 0; i < 4; i++)
#pragma unroll
        for (int u = 0; u < 4; u++) accp[i][u] = 0ull;

    float4 q0, q1, p0, p1;
    {
        const float* rowp = (xk < SDIM) ? (s + xrow * SDIM + xk)
                                        : (g_sagg + xrow * SDIM + (xk - SDIM));
        q0 = *(const float4*)rowp;
        q1 = *(const float4*)(rowp + 4);
    }
    __syncthreads();   // weights staged
    for (int kc = 0; kc < 16; kc++) {
        __syncthreads();
        Xs[(xk + 0) * 128 + xn] = q0.x;
        Xs[(xk + 1) * 128 + xn] = q0.y;
        Xs[(xk + 2) * 128 + xn] = q0.z;
        Xs[(xk + 3) * 128 + xn] = q0.w;
        Xs[(xk + 4) * 128 + xn] = q1.x;
        Xs[(xk + 5) * 128 + xn] = q1.y;
        Xs[(xk + 6) * 128 + xn] = q1.z;
        Xs[(xk + 7) * 128 + xn] = q1.w;
        if (kc < 15) {
            int kg = (kc + 1) * 16 + xk;
            const float* rowp = (kg < SDIM) ? (s + xrow * SDIM + kg)
                                            : (g_sagg + xrow * SDIM + (kg - SDIM));
            p0 = *(const float4*)rowp;
            p1 = *(const float4*)(rowp + 4);
        }
        __syncthreads();
#pragma unroll
        for (int kk = 0; kk < 16; kk++) {
            float4 bv = *(const float4*)&Ws1[(kc * 16 + kk) * HID + j0];
            u64 bp0 = pack2(bv.x), bp1 = pack2(bv.y), bp2 = pack2(bv.z), bp3 = pack2(bv.w);
            ulonglong2 A0 = *(const ulonglong2*)&Xs[kk * 128 + nb];
            ulonglong2 A1 = *(const ulonglong2*)&Xs[kk * 128 + nb + 4];
            u64 ap[4] = {A0.x, A0.y, A1.x, A1.y};
#pragma unroll
            for (int ip = 0; ip < 4; ip++) {
                fma2(accp[ip][0], ap[ip], bp0);
                fma2(accp[ip][1], ap[ip], bp1);
                fma2(accp[ip][2], ap[ip], bp2);
                fma2(accp[ip][3], ap[ip], bp3);
            }
        }
        q0 = p0; q1 = p1;
    }
    {
        float bb[4];
#pragma unroll
        for (int u = 0; u < 4; u++) bb[u] = bn1[j0 + u];
#pragma unroll
        for (int ip = 0; ip < 4; ip++) {
            float2 f[4];
#pragma unroll
            for (int u = 0; u < 4; u++) f[u] = u2f(accp[ip][u]);
            float4 o0, o1;
            o0.x = silu(f[0].x + bb[0]);
            o0.y = silu(f[1].x + bb[1]);
            o0.z = silu(f[2].x + bb[2]);
            o0.w = silu(f[3].x + bb[3]);
            o1.x = silu(f[0].y + bb[0]);
            o1.y = silu(f[1].y + bb[1]);
            o1.z = silu(f[2].y + bb[2]);
            o1.w = silu(f[3].y + bb[3]);
            *(float4*)&Us[(nb + 2 * ip) * 68 + j0]     = o0;
            *(float4*)&Us[(nb + 2 * ip + 1) * 68 + j0] = o1;
        }
    }
    __syncthreads();

    // ---------- GEMM-n2: U(128x64) @ Wn2(64x128), u-packed; s += out + bn2 ----------
    const int j3 = jt * 8;
    u64 acc3p[8][4];
#pragma unroll
    for (int i = 0; i < 8; i++)
#pragma unroll
        for (int u = 0; u < 4; u++) acc3p[i][u] = 0ull;
#pragma unroll 2
    for (int k = 0; k < HID; k++) {
        ulonglong2 B0 = *(const ulonglong2*)&Ws2[k * SDIM + j3];
        ulonglong2 B1 = *(const ulonglong2*)&Ws2[k * SDIM + j3 + 4];
        u64 bp[4] = {B0.x, B0.y, B1.x, B1.y};
#pragma unroll
        for (int i = 0; i < 8; i++) {
            u64 ap = pack2(Us[(nb + i) * 68 + k]);
            fma2(acc3p[i][0], ap, bp[0]);
            fma2(acc3p[i][1], ap, bp[1]);
            fma2(acc3p[i][2], ap, bp[2]);
            fma2(acc3p[i][3], ap, bp[3]);
        }
    }
    {
        float bb2[8];
#pragma unroll
        for (int u = 0; u < 8; u++) bb2[u] = bn2[j3 + u];
#pragma unroll
        for (int i = 0; i < 8; i++) {
            int n = n0 + nb + i;
            if (n < NNODE) {
                float* sp = s + (long)n * SDIM + j3;
                float4 v0 = *(float4*)&sp[0];
                float4 v1 = *(float4*)&sp[4];
                float2 f0 = u2f(acc3p[i][0]), f1 = u2f(acc3p[i][1]);
                float2 f2 = u2f(acc3p[i][2]), f3 = u2f(acc3p[i][3]);
                v0.x += f0.x + bb2[0]; v0.y += f0.y + bb2[1];
                v0.z += f1.x + bb2[2]; v0.w += f1.y + bb2[3];
                v1.x += f2.x + bb2[4]; v1.y += f2.y + bb2[5];
                v1.z += f3.x + bb2[6]; v1.w += f3.y + bb2[7];
                *(float4*)&sp[0] = v0;
                *(float4*)&sp[4] = v1;
            }
        }
    }
    // v += v_agg * inv_cnt
    if (tid < 128) {
        int n = n0 + tid;
        if (n < NNODE) {
            float ic = 1.0f / fmaxf(g_cnt[n], 1.0f);
            float* vp = v + (long)n * 9;
            const float* vap = g_vagg + (long)n * 9;
#pragma unroll
            for (int q = 0; q < 9; q++)
                vp[q] += vap[q] * ic;
        }
    }
}

// -------- launch --------
extern "C" void kernel_launch(void* const* d_in, const int* in_sizes, int n_in,
                              void* d_out, int out_size)
{
    const float* s_in = (const float*)d_in[0];
    const float* v_in = (const float*)d_in[1];
    const int*   ei   = (const int*)d_in[2];
    const float* dvec = (const float*)d_in[3];
    const float* r    = (const float*)d_in[4];
    const float* W1   = (const float*)d_in[5];
    const float* b1   = (const float*)d_in[6];
    const float* W2   = (const float*)d_in[7];
    const float* b2   = (const float*)d_in[8];
    const float* W3   = (const float*)d_in[9];
    const float* b3   = (const float*)d_in[10];
    const float* Wn1  = (const float*)d_in[11];
    const float* bn1  = (const float*)d_in[12];
    const float* Wn2  = (const float*)d_in[13];
    const float* bn2  = (const float*)d_in[14];

    float* s = (float*)d_out;
    float* v = s + (size_t)NNODE * SDIM;

    cudaFuncSetAttribute(edge_kernel, cudaFuncAttributeMaxDynamicSharedMemorySize,
                         EDGE_SMEM_FLOATS * 4);
    cudaFuncSetAttribute(node_kernel, cudaFuncAttributeMaxDynamicSharedMemorySize,
                         NODE_SMEM_FLOATS * 4);

    void *p_cnt, *p_sagg, *p_vagg;
    cudaGetSymbolAddress(&p_cnt, g_cnt);
    cudaGetSymbolAddress(&p_sagg, g_sagg);
    cudaGetSymbolAddress(&p_vagg, g_vagg);

    cudaMemcpyAsync(s, s_in, sizeof(float) * NNODE * SDIM, cudaMemcpyDeviceToDevice, 0);
    cudaMemcpyAsync(v, v_in, sizeof(float) * NNODE * 9, cudaMemcpyDeviceToDevice, 0);
    cudaMemsetAsync(p_cnt, 0, sizeof(float) * NNODE, 0);
    init_kernel<<<(NEDGE + 255) / 256, 256>>>(ei);

    for (int l = 0; l < NLAYER; l++) {
        cudaMemsetAsync(p_sagg, 0, sizeof(float) * NNODE * SDIM, 0);
        cudaMemsetAsync(p_vagg, 0, sizeof(float) * NNODE * 9, 0);
        edge_kernel<<<(NEDGE + TEB - 1) / TEB, NTH, EDGE_SMEM_FLOATS * 4>>>(
            s, v, ei, dvec, r,
            W1 + (size_t)l * K1DIM * HID, b1 + (size_t)l * HID,
            W2 + (size_t)l * HID * HID,   b2 + (size_t)l * HID,
            W3 + (size_t)l * HID * M3DIM, b3 + (size_t)l * M3DIM);
        node_kernel<<<(NNODE + 127) / 128, NTH, NODE_SMEM_FLOATS * 4>>>(
            s, v,
            Wn1 + (size_t)l * 2 * SDIM * HID, bn1 + (size_t)l * HID,
            Wn2 + (size_t)l * HID * SDIM,     bn2 + (size_t)l * SDIM);
    }
}

// round 7
// speedup vs baseline: 1.3094x; 1.2249x over previous
#include <cuda_runtime.h>
#include <math.h>

#define NNODE 50000
#define NEDGE 500000
#define SDIM 128
#define HID 64
#define NLAYER 4
#define M3DIM 134     // SD + 2*VD
#define K1DIM 257     // 2*SD + 1
#define TEB 128       // edges per block
#define NTH 256

typedef unsigned long long u64;

// -------- scratch (no cudaMalloc allowed) --------
__device__ float g_sagg[NNODE * SDIM];
__device__ float g_vagg[NNODE * 9];
__device__ float g_cnt[NNODE];

__device__ __forceinline__ float silu(float x) {
    return x / (1.0f + __expf(-x));
}
// packed f32x2 helpers
__device__ __forceinline__ u64 pack2(float x) {
    u64 r; asm("mov.b64 %0, {%1, %1};" : "=l"(r) : "f"(x)); return r;
}
__device__ __forceinline__ void fma2(u64& d, u64 a, u64 b) {
    asm("fma.rn.f32x2 %0, %1, %2, %0;" : "+l"(d) : "l"(a), "l"(b));
}
__device__ __forceinline__ float2 u2f(u64 x) {
    float2 f; asm("mov.b64 {%0, %1}, %2;" : "=f"(f.x), "=f"(f.y) : "l"(x)); return f;
}

// -------- in-degree counts --------
__global__ void init_kernel(const int* __restrict__ ei) {
    int e = blockIdx.x * blockDim.x + threadIdx.x;
    if (e < NEDGE) atomicAdd(&g_cnt[ei[e]], 1.0f);
}

// -------- fused edge kernel --------
// smem float offsets (total 112640 B -> 2 CTAs/SM)
#define EO_W2   0                // 64*64 = 4096
#define EO_H1   4096             // 128*68 = 8704
#define EO_H2   12800            // 128*68 = 8704
#define EO_STG  21504            // 2 stage buffers * (2048 X + 1024 W) = 6144
#define EO_IDST 27648            // 128 ints
#define EO_ISRC 27776
#define EO_C    27904
#define EO_D    28032
#define EDGE_SMEM_FLOATS 28160

__global__ void __launch_bounds__(NTH, 2) edge_kernel(
    const float* __restrict__ s, const float* __restrict__ v,
    const int* __restrict__ ei, const float* __restrict__ dvec,
    const float* __restrict__ r,
    const float* __restrict__ W1, const float* __restrict__ b1,
    const float* __restrict__ W2, const float* __restrict__ b2,
    const float* __restrict__ W3, const float* __restrict__ b3)
{
    extern __shared__ float sm[];
    float* Ws2 = sm + EO_W2;
    float* Hs1 = sm + EO_H1;
    float* Hs2 = sm + EO_H2;
    float* Stg = sm + EO_STG;
    int*   sdst = (int*)(sm + EO_IDST);
    int*   ssrc = (int*)(sm + EO_ISRC);
    float* sC   = sm + EO_C;
    float* sd   = sm + EO_D;

    const int tid = threadIdx.x;
    const int e0  = blockIdx.x * TEB;

    // stage W2 + edge metadata
    for (int i = tid; i < HID * HID; i += NTH) Ws2[i] = W2[i];
    if (tid < TEB) {
        int e  = e0 + tid;
        int ec = (e < NEDGE) ? e : 0;
        sdst[tid] = ei[ec];
        ssrc[tid] = ei[NEDGE + ec];
        float dv = dvec[ec];
        float C = 0.5f * (cosf(0.62831853071795864769f * dv) + 1.0f);
        if (!(dv < 5.0f)) C = 0.0f;
        sC[tid] = (e < NEDGE) ? C : 0.0f;
        sd[tid] = dv;
    }
    __syncthreads();

    const int jt = tid & 15;       // 16 j-groups
    const int et = tid >> 4;       // 16 edge-groups
    const int j0 = jt * 4;
    const int eb = et * 8;

    // X staging: thread -> (edge, k-offset); W staging: thread -> (k-row, 4 cols)
    const int xe = tid & 127;
    const int xk = (tid >> 7) * 8;
    const long xdst = sdst[xe];
    const long xsrc = ssrc[xe];
    const int wrow = tid >> 4;
    const int wcol = (tid & 15) * 4;

    // ---------- GEMM1: X(128x257) @ W1(257x64), edge-packed f32x2 ----------
    u64 accp[4][4];
#pragma unroll
    for (int i = 0; i < 4; i++)
#pragma unroll
        for (int u = 0; u < 4; u++) accp[i][u] = 0ull;

    float4 q0, q1, p0, p1, wq, wp;
    {
        const float* rowp = (xk < SDIM) ? (s + xdst * SDIM + xk)
                                        : (s + xsrc * SDIM + (xk - SDIM));
        q0 = *(const float4*)rowp;
        q1 = *(const float4*)(rowp + 4);
        wq = *(const float4*)&W1[wrow * HID + wcol];
        float* Xb = Stg;          // buffer 0: X
        float* Wb = Stg + 2048;   // buffer 0: W
        Xb[(xk + 0) * TEB + xe] = q0.x;
        Xb[(xk + 1) * TEB + xe] = q0.y;
        Xb[(xk + 2) * TEB + xe] = q0.z;
        Xb[(xk + 3) * TEB + xe] = q0.w;
        Xb[(xk + 4) * TEB + xe] = q1.x;
        Xb[(xk + 5) * TEB + xe] = q1.y;
        Xb[(xk + 6) * TEB + xe] = q1.z;
        Xb[(xk + 7) * TEB + xe] = q1.w;
        *(float4*)&Wb[wrow * HID + wcol] = wq;
    }
    for (int kc = 0; kc < 16; kc++) {
        const float* Xc = Stg + (kc & 1) * 3072;
        const float* Wc = Xc + 2048;
        if (kc < 15) {    // prefetch next chunk (LDG issued before barrier)
            int kg = (kc + 1) * 16 + xk;
            const float* rowp = (kg < SDIM) ? (s + xdst * SDIM + kg)
                                            : (s + xsrc * SDIM + (kg - SDIM));
            p0 = *(const float4*)rowp;
            p1 = *(const float4*)(rowp + 4);
            wp = *(const float4*)&W1[((kc + 1) * 16 + wrow) * HID + wcol];
        }
        __syncthreads();
#pragma unroll
        for (int kk = 0; kk < 16; kk++) {
            float4 bv = *(const float4*)&Wc[kk * HID + j0];
            u64 bp0 = pack2(bv.x), bp1 = pack2(bv.y), bp2 = pack2(bv.z), bp3 = pack2(bv.w);
            ulonglong2 A0 = *(const ulonglong2*)&Xc[kk * TEB + eb];
            ulonglong2 A1 = *(const ulonglong2*)&Xc[kk * TEB + eb + 4];
            u64 ap[4] = {A0.x, A0.y, A1.x, A1.y};
#pragma unroll
            for (int ip = 0; ip < 4; ip++) {
                fma2(accp[ip][0], ap[ip], bp0);
                fma2(accp[ip][1], ap[ip], bp1);
                fma2(accp[ip][2], ap[ip], bp2);
                fma2(accp[ip][3], ap[ip], bp3);
            }
        }
        if (kc < 15) {
            float* Xn = Stg + ((kc + 1) & 1) * 3072;
            float* Wn = Xn + 2048;
            Xn[(xk + 0) * TEB + xe] = p0.x;
            Xn[(xk + 1) * TEB + xe] = p0.y;
            Xn[(xk + 2) * TEB + xe] = p0.z;
            Xn[(xk + 3) * TEB + xe] = p0.w;
            Xn[(xk + 4) * TEB + xe] = p1.x;
            Xn[(xk + 5) * TEB + xe] = p1.y;
            Xn[(xk + 6) * TEB + xe] = p1.z;
            Xn[(xk + 7) * TEB + xe] = p1.w;
            *(float4*)&Wn[wrow * HID + wcol] = wp;
        }
    }
    // epilogue: + d*W1[256] + b1, silu
    {
        float4 wl = *(const float4*)&W1[256 * HID + j0];
        float4 bbv = *(const float4*)&b1[j0];
        float wlast[4] = {wl.x, wl.y, wl.z, wl.w};
        float bb[4] = {bbv.x, bbv.y, bbv.z, bbv.w};
#pragma unroll
        for (int ip = 0; ip < 4; ip++) {
            float2 f[4];
#pragma unroll
            for (int u = 0; u < 4; u++) f[u] = u2f(accp[ip][u]);
            float dd0 = sd[eb + 2 * ip], dd1 = sd[eb + 2 * ip + 1];
            float4 o0, o1;
            o0.x = silu(f[0].x + dd0 * wlast[0] + bb[0]);
            o0.y = silu(f[1].x + dd0 * wlast[1] + bb[1]);
            o0.z = silu(f[2].x + dd0 * wlast[2] + bb[2]);
            o0.w = silu(f[3].x + dd0 * wlast[3] + bb[3]);
            o1.x = silu(f[0].y + dd1 * wlast[0] + bb[0]);
            o1.y = silu(f[1].y + dd1 * wlast[1] + bb[1]);
            o1.z = silu(f[2].y + dd1 * wlast[2] + bb[2]);
            o1.w = silu(f[3].y + dd1 * wlast[3] + bb[3]);
            *(float4*)&Hs1[(eb + 2 * ip) * 68 + j0]     = o0;
            *(float4*)&Hs1[(eb + 2 * ip + 1) * 68 + j0] = o1;
        }
    }
    __syncthreads();

    // ---------- GEMM2: H1(128x64) @ W2(64x64), col-packed ----------
    u64 acc2p[8][2];
#pragma unroll
    for (int i = 0; i < 8; i++) { acc2p[i][0] = 0ull; acc2p[i][1] = 0ull; }
#pragma unroll 4
    for (int k = 0; k < HID; k++) {
        ulonglong2 bvp = *(const ulonglong2*)&Ws2[k * HID + j0];
#pragma unroll
        for (int i = 0; i < 8; i++) {
            u64 ap = pack2(Hs1[(eb + i) * 68 + k]);
            fma2(acc2p[i][0], ap, bvp.x);
            fma2(acc2p[i][1], ap, bvp.y);
        }
    }
    {
        float4 bbv = *(const float4*)&b2[j0];
        float bb[4] = {bbv.x, bbv.y, bbv.z, bbv.w};
#pragma unroll
        for (int i = 0; i < 8; i++) {
            float2 f0 = u2f(acc2p[i][0]), f1 = u2f(acc2p[i][1]);
            float4 o;
            o.x = silu(f0.x + bb[0]);
            o.y = silu(f0.y + bb[1]);
            o.z = silu(f1.x + bb[2]);
            o.w = silu(f1.y + bb[3]);
            *(float4*)&Hs2[(eb + i) * 68 + j0] = o;
        }
    }
    __syncthreads();

    // ---------- GEMM3: H2(128x64) @ W3(64x134), weights from gmem (L2) ----------
    const int j3 = jt * 8;      // first 128 cols (ms)
    u64 acc3p[8][4];
#pragma unroll
    for (int i = 0; i < 8; i++)
#pragma unroll
        for (int u = 0; u < 4; u++) acc3p[i][u] = 0ull;
#pragma unroll 2
    for (int k = 0; k < HID; k++) {
        const float* wr = W3 + k * M3DIM + j3;     // 8B-aligned (134*4 % 8 == 0)
        u64 bp[4];
        bp[0] = *(const u64*)(wr + 0);
        bp[1] = *(const u64*)(wr + 2);
        bp[2] = *(const u64*)(wr + 4);
        bp[3] = *(const u64*)(wr + 6);
#pragma unroll
        for (int i = 0; i < 8; i++) {
            u64 ap = pack2(Hs2[(eb + i) * 68 + k]);
            fma2(acc3p[i][0], ap, bp[0]);
            fma2(acc3p[i][1], ap, bp[1]);
            fma2(acc3p[i][2], ap, bp[2]);
            fma2(acc3p[i][3], ap, bp[3]);
        }
    }
    // scatter ms * C into s_agg
    {
        float bb3[8];
#pragma unroll
        for (int u = 0; u < 8; u++) bb3[u] = b3[j3 + u];
#pragma unroll
        for (int i = 0; i < 8; i++) {
            int e = e0 + eb + i;
            if (e < NEDGE) {
                float Cv = sC[eb + i];
                float* sa = g_sagg + (long)sdst[eb + i] * SDIM + j3;
#pragma unroll
                for (int u = 0; u < 4; u++) {
                    float2 f = u2f(acc3p[i][u]);
                    atomicAdd(&sa[2 * u],     (f.x + bb3[2 * u])     * Cv);
                    atomicAdd(&sa[2 * u + 1], (f.y + bb3[2 * u + 1]) * Cv);
                }
            }
        }
    }

    // ---- gv/gr (cols 128..133): 256 threads compute, 128 scatter ----
    {
        float* sG = Stg;   // reuse stage region
        const int te = tid & 127;
        const int th = tid >> 7;     // 0 -> gv, 1 -> gr
#pragma unroll
        for (int u = 0; u < 3; u++) {
            int col = 128 + th * 3 + u;
            float a = b3[col];
#pragma unroll 8
            for (int k = 0; k < HID; k++)
                a = fmaf(Hs2[te * 68 + k], W3[k * M3DIM + col], a);
            sG[te * 6 + th * 3 + u] = a;
        }
        __syncthreads();
        if (tid < TEB) {
            int e = e0 + tid;
            if (e < NEDGE) {
                float Cv = sC[tid];
                long srcn = ssrc[tid];
                long dstn = sdst[tid];
                float r0 = r[(long)e * 3 + 0];
                float r1 = r[(long)e * 3 + 1];
                float r2 = r[(long)e * 3 + 2];
                const float* vs = v + srcn * 9;
                float* va = g_vagg + dstn * 9;
#pragma unroll
                for (int i = 0; i < 3; i++) {
                    float gvi = sG[tid * 6 + i], gri = sG[tid * 6 + 3 + i];
                    atomicAdd(&va[i * 3 + 0], (vs[i * 3 + 0] * gvi + r0 * gri) * Cv);
                    atomicAdd(&va[i * 3 + 1], (vs[i * 3 + 1] * gvi + r1 * gri) * Cv);
                    atomicAdd(&va[i * 3 + 2], (vs[i * 3 + 2] * gvi + r2 * gri) * Cv);
                }
            }
        }
    }
}

// -------- fused node kernel --------
// smem float offsets (total 92160 B -> 2 CTAs/SM)
#define NO_W2  0                 // 64*128 = 8192
#define NO_U   8192              // 128*68 = 8704
#define NO_STG 16896             // 6144
#define NODE_SMEM_FLOATS 23040

__global__ void __launch_bounds__(NTH, 2) node_kernel(
    float* __restrict__ s, float* __restrict__ v,
    const float* __restrict__ Wn1, const float* __restrict__ bn1,
    const float* __restrict__ Wn2, const float* __restrict__ bn2)
{
    extern __shared__ float sm[];
    float* Ws2 = sm + NO_W2;
    float* Us  = sm + NO_U;
    float* Stg = sm + NO_STG;

    const int tid = threadIdx.x;
    const int n0  = blockIdx.x * 128;

    for (int i = tid; i < HID * SDIM; i += NTH) Ws2[i] = Wn2[i];

    const int jt = tid & 15, et = tid >> 4;
    const int j0 = jt * 4,  nb = et * 8;
    const int xn = tid & 127;
    const int xk = (tid >> 7) * 8;
    int xcl = n0 + xn; if (xcl > NNODE - 1) xcl = NNODE - 1;
    const long xrow = (long)xcl;
    const int wrow = tid >> 4;
    const int wcol = (tid & 15) * 4;

    // ---------- GEMM-n1: [s|s_agg](128x256) @ Wn1(256x64) ----------
    u64 accp[4][4];
#pragma unroll
    for (int i = 0; i < 4; i++)
#pragma unroll
        for (int u = 0; u < 4; u++) accp[i][u] = 0ull;

    float4 q0, q1, p0, p1, wq, wp;
    {
        const float* rowp = (xk < SDIM) ? (s + xrow * SDIM + xk)
                                        : (g_sagg + xrow * SDIM + (xk - SDIM));
        q0 = *(const float4*)rowp;
        q1 = *(const float4*)(rowp + 4);
        wq = *(const float4*)&Wn1[wrow * HID + wcol];
        float* Xb = Stg;
        float* Wb = Stg + 2048;
        Xb[(xk + 0) * 128 + xn] = q0.x;
        Xb[(xk + 1) * 128 + xn] = q0.y;
        Xb[(xk + 2) * 128 + xn] = q0.z;
        Xb[(xk + 3) * 128 + xn] = q0.w;
        Xb[(xk + 4) * 128 + xn] = q1.x;
        Xb[(xk + 5) * 128 + xn] = q1.y;
        Xb[(xk + 6) * 128 + xn] = q1.z;
        Xb[(xk + 7) * 128 + xn] = q1.w;
        *(float4*)&Wb[wrow * HID + wcol] = wq;
    }
    for (int kc = 0; kc < 16; kc++) {
        const float* Xc = Stg + (kc & 1) * 3072;
        const float* Wc = Xc + 2048;
        if (kc < 15) {
            int kg = (kc + 1) * 16 + xk;
            const float* rowp = (kg < SDIM) ? (s + xrow * SDIM + kg)
                                            : (g_sagg + xrow * SDIM + (kg - SDIM));
            p0 = *(const float4*)rowp;
            p1 = *(const float4*)(rowp + 4);
            wp = *(const float4*)&Wn1[((kc + 1) * 16 + wrow) * HID + wcol];
        }
        __syncthreads();
#pragma unroll
        for (int kk = 0; kk < 16; kk++) {
            float4 bv = *(const float4*)&Wc[kk * HID + j0];
            u64 bp0 = pack2(bv.x), bp1 = pack2(bv.y), bp2 = pack2(bv.z), bp3 = pack2(bv.w);
            ulonglong2 A0 = *(const ulonglong2*)&Xc[kk * 128 + nb];
            ulonglong2 A1 = *(const ulonglong2*)&Xc[kk * 128 + nb + 4];
            u64 ap[4] = {A0.x, A0.y, A1.x, A1.y};
#pragma unroll
            for (int ip = 0; ip < 4; ip++) {
                fma2(accp[ip][0], ap[ip], bp0);
                fma2(accp[ip][1], ap[ip], bp1);
                fma2(accp[ip][2], ap[ip], bp2);
                fma2(accp[ip][3], ap[ip], bp3);
            }
        }
        if (kc < 15) {
            float* Xn = Stg + ((kc + 1) & 1) * 3072;
            float* Wn = Xn + 2048;
            Xn[(xk + 0) * 128 + xn] = p0.x;
            Xn[(xk + 1) * 128 + xn] = p0.y;
            Xn[(xk + 2) * 128 + xn] = p0.z;
            Xn[(xk + 3) * 128 + xn] = p0.w;
            Xn[(xk + 4) * 128 + xn] = p1.x;
            Xn[(xk + 5) * 128 + xn] = p1.y;
            Xn[(xk + 6) * 128 + xn] = p1.z;
            Xn[(xk + 7) * 128 + xn] = p1.w;
            *(float4*)&Wn[wrow * HID + wcol] = wp;
        }
    }
    {
        float4 bbv = *(const float4*)&bn1[j0];
        float bb[4] = {bbv.x, bbv.y, bbv.z, bbv.w};
#pragma unroll
        for (int ip = 0; ip < 4; ip++) {
            float2 f[4];
#pragma unroll
            for (int u = 0; u < 4; u++) f[u] = u2f(accp[ip][u]);
            float4 o0, o1;
            o0.x = silu(f[0].x + bb[0]);
            o0.y = silu(f[1].x + bb[1]);
            o0.z = silu(f[2].x + bb[2]);
            o0.w = silu(f[3].x + bb[3]);
            o1.x = silu(f[0].y + bb[0]);
            o1.y = silu(f[1].y + bb[1]);
            o1.z = silu(f[2].y + bb[2]);
            o1.w = silu(f[3].y + bb[3]);
            *(float4*)&Us[(nb + 2 * ip) * 68 + j0]     = o0;
            *(float4*)&Us[(nb + 2 * ip + 1) * 68 + j0] = o1;
        }
    }
    __syncthreads();

    // ---------- GEMM-n2: U(128x64) @ Wn2(64x128); s += out + bn2 ----------
    const int j3 = jt * 8;
    u64 acc3p[8][4];
#pragma unroll
    for (int i = 0; i < 8; i++)
#pragma unroll
        for (int u = 0; u < 4; u++) acc3p[i][u] = 0ull;
#pragma unroll 2
    for (int k = 0; k < HID; k++) {
        ulonglong2 B0 = *(const ulonglong2*)&Ws2[k * SDIM + j3];
        ulonglong2 B1 = *(const ulonglong2*)&Ws2[k * SDIM + j3 + 4];
        u64 bp[4] = {B0.x, B0.y, B1.x, B1.y};
#pragma unroll
        for (int i = 0; i < 8; i++) {
            u64 ap = pack2(Us[(nb + i) * 68 + k]);
            fma2(acc3p[i][0], ap, bp[0]);
            fma2(acc3p[i][1], ap, bp[1]);
            fma2(acc3p[i][2], ap, bp[2]);
            fma2(acc3p[i][3], ap, bp[3]);
        }
    }
    {
        float bb2[8];
#pragma unroll
        for (int u = 0; u < 8; u++) bb2[u] = bn2[j3 + u];
#pragma unroll
        for (int i = 0; i < 8; i++) {
            int n = n0 + nb + i;
            if (n < NNODE) {
                float* sp = s + (long)n * SDIM + j3;
                float4 v0 = *(float4*)&sp[0];
                float4 v1 = *(float4*)&sp[4];
                float2 f0 = u2f(acc3p[i][0]), f1 = u2f(acc3p[i][1]);
                float2 f2 = u2f(acc3p[i][2]), f3 = u2f(acc3p[i][3]);
                v0.x += f0.x + bb2[0]; v0.y += f0.y + bb2[1];
                v0.z += f1.x + bb2[2]; v0.w += f1.y + bb2[3];
                v1.x += f2.x + bb2[4]; v1.y += f2.y + bb2[5];
                v1.z += f3.x + bb2[6]; v1.w += f3.y + bb2[7];
                *(float4*)&sp[0] = v0;
                *(float4*)&sp[4] = v1;
            }
        }
    }
    // v += v_agg * inv_cnt
    if (tid < 128) {
        int n = n0 + tid;
        if (n < NNODE) {
            float ic = 1.0f / fmaxf(g_cnt[n], 1.0f);
            float* vp = v + (long)n * 9;
            const float* vap = g_vagg + (long)n * 9;
#pragma unroll
            for (int q = 0; q < 9; q++)
                vp[q] += vap[q] * ic;
        }
    }
}

// -------- launch --------
extern "C" void kernel_launch(void* const* d_in, const int* in_sizes, int n_in,
                              void* d_out, int out_size)
{
    const float* s_in = (const float*)d_in[0];
    const float* v_in = (const float*)d_in[1];
    const int*   ei   = (const int*)d_in[2];
    const float* dvec = (const float*)d_in[3];
    const float* r    = (const float*)d_in[4];
    const float* W1   = (const float*)d_in[5];
    const float* b1   = (const float*)d_in[6];
    const float* W2   = (const float*)d_in[7];
    const float* b2   = (const float*)d_in[8];
    const float* W3   = (const float*)d_in[9];
    const float* b3   = (const float*)d_in[10];
    const float* Wn1  = (const float*)d_in[11];
    const float* bn1  = (const float*)d_in[12];
    const float* Wn2  = (const float*)d_in[13];
    const float* bn2  = (const float*)d_in[14];

    float* s = (float*)d_out;
    float* v = s + (size_t)NNODE * SDIM;

    cudaFuncSetAttribute(edge_kernel, cudaFuncAttributeMaxDynamicSharedMemorySize,
                         EDGE_SMEM_FLOATS * 4);
    cudaFuncSetAttribute(node_kernel, cudaFuncAttributeMaxDynamicSharedMemorySize,
                         NODE_SMEM_FLOATS * 4);

    void *p_cnt, *p_sagg, *p_vagg;
    cudaGetSymbolAddress(&p_cnt, g_cnt);
    cudaGetSymbolAddress(&p_sagg, g_sagg);
    cudaGetSymbolAddress(&p_vagg, g_vagg);

    cudaMemcpyAsync(s, s_in, sizeof(float) * NNODE * SDIM, cudaMemcpyDeviceToDevice, 0);
    cudaMemcpyAsync(v, v_in, sizeof(float) * NNODE * 9, cudaMemcpyDeviceToDevice, 0);
    cudaMemsetAsync(p_cnt, 0, sizeof(float) * NNODE, 0);
    init_kernel<<<(NEDGE + 255) / 256, 256>>>(ei);

    for (int l = 0; l < NLAYER; l++) {
        cudaMemsetAsync(p_sagg, 0, sizeof(float) * NNODE * SDIM, 0);
        cudaMemsetAsync(p_vagg, 0, sizeof(float) * NNODE * 9, 0);
        edge_kernel<<<(NEDGE + TEB - 1) / TEB, NTH, EDGE_SMEM_FLOATS * 4>>>(
            s, v, ei, dvec, r,
            W1 + (size_t)l * K1DIM * HID, b1 + (size_t)l * HID,
            W2 + (size_t)l * HID * HID,   b2 + (size_t)l * HID,
            W3 + (size_t)l * HID * M3DIM, b3 + (size_t)l * M3DIM);
        node_kernel<<<(NNODE + 127) / 128, NTH, NODE_SMEM_FLOATS * 4>>>(
            s, v,
            Wn1 + (size_t)l * 2 * SDIM * HID, bn1 + (size_t)l * HID,
            Wn2 + (size_t)l * HID * SDIM,     bn2 + (size_t)l * SDIM);
    }
}

// round 8
// speedup vs baseline: 1.5883x; 1.2130x over previous
#include <cuda_runtime.h>
#include <math.h>

#define NNODE 50000
#define NEDGE 500000
#define SDIM 128
#define HID 64
#define NLAYER 4
#define M3DIM 134     // SD + 2*VD
#define K1DIM 257     // 2*SD + 1
#define TEB 128       // edges per block
#define NTH 256

typedef unsigned long long u64;

// -------- scratch (no cudaMalloc allowed) --------
__device__ float g_sagg[NNODE * SDIM];
__device__ float g_vagg[NNODE * 9];
__device__ float g_cnt[NNODE];

__device__ __forceinline__ float silu(float x) {
    return x / (1.0f + __expf(-x));
}
// packed f32x2 helpers
__device__ __forceinline__ u64 pack2(float x) {
    u64 r; asm("mov.b64 %0, {%1, %1};" : "=l"(r) : "f"(x)); return r;
}
__device__ __forceinline__ void fma2(u64& d, u64 a, u64 b) {
    asm("fma.rn.f32x2 %0, %1, %2, %0;" : "+l"(d) : "l"(a), "l"(b));
}
__device__ __forceinline__ float2 u2f(u64 x) {
    float2 f; asm("mov.b64 {%0, %1}, %2;" : "=f"(f.x), "=f"(f.y) : "l"(x)); return f;
}
// vectorized global reduction (sm_90+)
__device__ __forceinline__ void red_add_v4(float* p, float a, float b, float c, float d) {
    asm volatile("red.global.add.v4.f32 [%0], {%1, %2, %3, %4};"
                 :: "l"(p), "f"(a), "f"(b), "f"(c), "f"(d) : "memory");
}

// -------- in-degree counts --------
__global__ void init_kernel(const int* __restrict__ ei) {
    int e = blockIdx.x * blockDim.x + threadIdx.x;
    if (e < NEDGE) atomicAdd(&g_cnt[ei[e]], 1.0f);
}

// -------- fused edge kernel --------
// smem float offsets (total 112640 B -> 2 CTAs/SM)
#define EO_W2   0                // 64*64 = 4096
#define EO_H1   4096             // 128*68 = 8704
#define EO_H2   12800            // 128*68 = 8704
#define EO_STG  21504            // 2 stage buffers * (2048 X + 1024 W) = 6144
#define EO_IDST 27648            // 128 ints
#define EO_ISRC 27776
#define EO_C    27904
#define EO_D    28032
#define EDGE_SMEM_FLOATS 28160

__global__ void __launch_bounds__(NTH, 2) edge_kernel(
    const float* __restrict__ s, const float* __restrict__ v,
    const int* __restrict__ ei, const float* __restrict__ dvec,
    const float* __restrict__ r,
    const float* __restrict__ W1, const float* __restrict__ b1,
    const float* __restrict__ W2, const float* __restrict__ b2,
    const float* __restrict__ W3, const float* __restrict__ b3)
{
    extern __shared__ float sm[];
    float* Ws2 = sm + EO_W2;
    float* Hs1 = sm + EO_H1;
    float* Hs2 = sm + EO_H2;
    float* Stg = sm + EO_STG;
    int*   sdst = (int*)(sm + EO_IDST);
    int*   ssrc = (int*)(sm + EO_ISRC);
    float* sC   = sm + EO_C;
    float* sd   = sm + EO_D;

    const int tid = threadIdx.x;
    const int e0  = blockIdx.x * TEB;

    // stage W2 + edge metadata
    for (int i = tid; i < HID * HID; i += NTH) Ws2[i] = W2[i];
    if (tid < TEB) {
        int e  = e0 + tid;
        int ec = (e < NEDGE) ? e : 0;
        sdst[tid] = ei[ec];
        ssrc[tid] = ei[NEDGE + ec];
        float dv = dvec[ec];
        float C = 0.5f * (cosf(0.62831853071795864769f * dv) + 1.0f);
        if (!(dv < 5.0f)) C = 0.0f;
        sC[tid] = (e < NEDGE) ? C : 0.0f;
        sd[tid] = dv;
    }
    __syncthreads();

    const int jt = tid & 15;       // 16 j-groups
    const int et = tid >> 4;       // 16 edge-groups
    const int j0 = jt * 4;
    const int eb = et * 8;

    // X staging: thread -> (edge, k-offset); W staging: thread -> (k-row, 4 cols)
    const int xe = tid & 127;
    const int xk = (tid >> 7) * 8;
    const long xdst = sdst[xe];
    const long xsrc = ssrc[xe];
    const int wrow = tid >> 4;
    const int wcol = (tid & 15) * 4;

    // ---------- GEMM1: X(128x257) @ W1(257x64), edge-packed f32x2 ----------
    u64 accp[4][4];
#pragma unroll
    for (int i = 0; i < 4; i++)
#pragma unroll
        for (int u = 0; u < 4; u++) accp[i][u] = 0ull;

    float4 q0, q1, p0, p1, wq, wp;
    {
        const float* rowp = (xk < SDIM) ? (s + xdst * SDIM + xk)
                                        : (s + xsrc * SDIM + (xk - SDIM));
        q0 = *(const float4*)rowp;
        q1 = *(const float4*)(rowp + 4);
        wq = *(const float4*)&W1[wrow * HID + wcol];
        float* Xb = Stg;          // buffer 0: X
        float* Wb = Stg + 2048;   // buffer 0: W
        Xb[(xk + 0) * TEB + xe] = q0.x;
        Xb[(xk + 1) * TEB + xe] = q0.y;
        Xb[(xk + 2) * TEB + xe] = q0.z;
        Xb[(xk + 3) * TEB + xe] = q0.w;
        Xb[(xk + 4) * TEB + xe] = q1.x;
        Xb[(xk + 5) * TEB + xe] = q1.y;
        Xb[(xk + 6) * TEB + xe] = q1.z;
        Xb[(xk + 7) * TEB + xe] = q1.w;
        *(float4*)&Wb[wrow * HID + wcol] = wq;
    }
    for (int kc = 0; kc < 16; kc++) {
        const float* Xc = Stg + (kc & 1) * 3072;
        const float* Wc = Xc + 2048;
        if (kc < 15) {    // prefetch next chunk (LDG issued before barrier)
            int kg = (kc + 1) * 16 + xk;
            const float* rowp = (kg < SDIM) ? (s + xdst * SDIM + kg)
                                            : (s + xsrc * SDIM + (kg - SDIM));
            p0 = *(const float4*)rowp;
            p1 = *(const float4*)(rowp + 4);
            wp = *(const float4*)&W1[((kc + 1) * 16 + wrow) * HID + wcol];
        }
        __syncthreads();
#pragma unroll
        for (int kk = 0; kk < 16; kk++) {
            float4 bv = *(const float4*)&Wc[kk * HID + j0];
            u64 bp0 = pack2(bv.x), bp1 = pack2(bv.y), bp2 = pack2(bv.z), bp3 = pack2(bv.w);
            ulonglong2 A0 = *(const ulonglong2*)&Xc[kk * TEB + eb];
            ulonglong2 A1 = *(const ulonglong2*)&Xc[kk * TEB + eb + 4];
            u64 ap[4] = {A0.x, A0.y, A1.x, A1.y};
#pragma unroll
            for (int ip = 0; ip < 4; ip++) {
                fma2(accp[ip][0], ap[ip], bp0);
                fma2(accp[ip][1], ap[ip], bp1);
                fma2(accp[ip][2], ap[ip], bp2);
                fma2(accp[ip][3], ap[ip], bp3);
            }
        }
        if (kc < 15) {
            float* Xn = Stg + ((kc + 1) & 1) * 3072;
            float* Wn = Xn + 2048;
            Xn[(xk + 0) * TEB + xe] = p0.x;
            Xn[(xk + 1) * TEB + xe] = p0.y;
            Xn[(xk + 2) * TEB + xe] = p0.z;
            Xn[(xk + 3) * TEB + xe] = p0.w;
            Xn[(xk + 4) * TEB + xe] = p1.x;
            Xn[(xk + 5) * TEB + xe] = p1.y;
            Xn[(xk + 6) * TEB + xe] = p1.z;
            Xn[(xk + 7) * TEB + xe] = p1.w;
            *(float4*)&Wn[wrow * HID + wcol] = wp;
        }
    }
    // epilogue: + d*W1[256] + b1, silu
    {
        float4 wl = *(const float4*)&W1[256 * HID + j0];
        float4 bbv = *(const float4*)&b1[j0];
        float wlast[4] = {wl.x, wl.y, wl.z, wl.w};
        float bb[4] = {bbv.x, bbv.y, bbv.z, bbv.w};
#pragma unroll
        for (int ip = 0; ip < 4; ip++) {
            float2 f[4];
#pragma unroll
            for (int u = 0; u < 4; u++) f[u] = u2f(accp[ip][u]);
            float dd0 = sd[eb + 2 * ip], dd1 = sd[eb + 2 * ip + 1];
            float4 o0, o1;
            o0.x = silu(f[0].x + dd0 * wlast[0] + bb[0]);
            o0.y = silu(f[1].x + dd0 * wlast[1] + bb[1]);
            o0.z = silu(f[2].x + dd0 * wlast[2] + bb[2]);
            o0.w = silu(f[3].x + dd0 * wlast[3] + bb[3]);
            o1.x = silu(f[0].y + dd1 * wlast[0] + bb[0]);
            o1.y = silu(f[1].y + dd1 * wlast[1] + bb[1]);
            o1.z = silu(f[2].y + dd1 * wlast[2] + bb[2]);
            o1.w = silu(f[3].y + dd1 * wlast[3] + bb[3]);
            *(float4*)&Hs1[(eb + 2 * ip) * 68 + j0]     = o0;
            *(float4*)&Hs1[(eb + 2 * ip + 1) * 68 + j0] = o1;
        }
    }
    __syncthreads();

    // ---------- GEMM2: H1(128x64) @ W2(64x64), col-packed, k-paired ----------
    u64 acc2p[8][2];
#pragma unroll
    for (int i = 0; i < 8; i++) { acc2p[i][0] = 0ull; acc2p[i][1] = 0ull; }
#pragma unroll 4
    for (int kq = 0; kq < 32; kq++) {
        ulonglong2 bv0 = *(const ulonglong2*)&Ws2[(2 * kq) * HID + j0];
        ulonglong2 bv1 = *(const ulonglong2*)&Ws2[(2 * kq + 1) * HID + j0];
#pragma unroll
        for (int i = 0; i < 8; i++) {
            float2 a2 = *(const float2*)&Hs1[(eb + i) * 68 + 2 * kq];
            u64 ap0 = pack2(a2.x), ap1 = pack2(a2.y);
            fma2(acc2p[i][0], ap0, bv0.x);
            fma2(acc2p[i][1], ap0, bv0.y);
            fma2(acc2p[i][0], ap1, bv1.x);
            fma2(acc2p[i][1], ap1, bv1.y);
        }
    }
    {
        float4 bbv = *(const float4*)&b2[j0];
        float bb[4] = {bbv.x, bbv.y, bbv.z, bbv.w};
#pragma unroll
        for (int i = 0; i < 8; i++) {
            float2 f0 = u2f(acc2p[i][0]), f1 = u2f(acc2p[i][1]);
            float4 o;
            o.x = silu(f0.x + bb[0]);
            o.y = silu(f0.y + bb[1]);
            o.z = silu(f1.x + bb[2]);
            o.w = silu(f1.y + bb[3]);
            *(float4*)&Hs2[(eb + i) * 68 + j0] = o;
        }
    }
    __syncthreads();

    // ---------- GEMM3: H2(128x64) @ W3(64x134), weights from gmem (L2), k-paired ----------
    const int j3 = jt * 8;      // first 128 cols (ms)
    u64 acc3p[8][4];
#pragma unroll
    for (int i = 0; i < 8; i++)
#pragma unroll
        for (int u = 0; u < 4; u++) acc3p[i][u] = 0ull;
#pragma unroll 2
    for (int kq = 0; kq < 32; kq++) {
        const float* wr0 = W3 + (2 * kq) * M3DIM + j3;       // 8B-aligned
        const float* wr1 = W3 + (2 * kq + 1) * M3DIM + j3;
        u64 b0[4], b1v[4];
#pragma unroll
        for (int u = 0; u < 4; u++) {
            b0[u]  = *(const u64*)(wr0 + 2 * u);
            b1v[u] = *(const u64*)(wr1 + 2 * u);
        }
#pragma unroll
        for (int i = 0; i < 8; i++) {
            float2 a2 = *(const float2*)&Hs2[(eb + i) * 68 + 2 * kq];
            u64 ap0 = pack2(a2.x), ap1 = pack2(a2.y);
            fma2(acc3p[i][0], ap0, b0[0]);
            fma2(acc3p[i][1], ap0, b0[1]);
            fma2(acc3p[i][2], ap0, b0[2]);
            fma2(acc3p[i][3], ap0, b0[3]);
            fma2(acc3p[i][0], ap1, b1v[0]);
            fma2(acc3p[i][1], ap1, b1v[1]);
            fma2(acc3p[i][2], ap1, b1v[2]);
            fma2(acc3p[i][3], ap1, b1v[3]);
        }
    }
    // scatter ms * C into s_agg (vector reductions)
    {
        float bb3[8];
#pragma unroll
        for (int u = 0; u < 8; u++) bb3[u] = b3[j3 + u];
#pragma unroll
        for (int i = 0; i < 8; i++) {
            int e = e0 + eb + i;
            if (e < NEDGE) {
                float Cv = sC[eb + i];
                float* sa = g_sagg + (long)sdst[eb + i] * SDIM + j3;
                float2 f0 = u2f(acc3p[i][0]), f1 = u2f(acc3p[i][1]);
                float2 f2 = u2f(acc3p[i][2]), f3 = u2f(acc3p[i][3]);
                red_add_v4(sa,
                           (f0.x + bb3[0]) * Cv, (f0.y + bb3[1]) * Cv,
                           (f1.x + bb3[2]) * Cv, (f1.y + bb3[3]) * Cv);
                red_add_v4(sa + 4,
                           (f2.x + bb3[4]) * Cv, (f2.y + bb3[5]) * Cv,
                           (f3.x + bb3[6]) * Cv, (f3.y + bb3[7]) * Cv);
            }
        }
    }

    // ---- gv/gr (cols 128..133): 256 threads compute, 128 scatter ----
    {
        float* sG = Stg;   // reuse stage region
        const int te = tid & 127;
        const int th = tid >> 7;     // 0 -> gv, 1 -> gr
#pragma unroll
        for (int u = 0; u < 3; u++) {
            int col = 128 + th * 3 + u;
            float a = b3[col];
#pragma unroll 8
            for (int k = 0; k < HID; k++)
                a = fmaf(Hs2[te * 68 + k], W3[k * M3DIM + col], a);
            sG[te * 6 + th * 3 + u] = a;
        }
        __syncthreads();
        if (tid < TEB) {
            int e = e0 + tid;
            if (e < NEDGE) {
                float Cv = sC[tid];
                long srcn = ssrc[tid];
                long dstn = sdst[tid];
                float r0 = r[(long)e * 3 + 0];
                float r1 = r[(long)e * 3 + 1];
                float r2 = r[(long)e * 3 + 2];
                const float* vs = v + srcn * 9;
                float* va = g_vagg + dstn * 9;
#pragma unroll
                for (int i = 0; i < 3; i++) {
                    float gvi = sG[tid * 6 + i], gri = sG[tid * 6 + 3 + i];
                    atomicAdd(&va[i * 3 + 0], (vs[i * 3 + 0] * gvi + r0 * gri) * Cv);
                    atomicAdd(&va[i * 3 + 1], (vs[i * 3 + 1] * gvi + r1 * gri) * Cv);
                    atomicAdd(&va[i * 3 + 2], (vs[i * 3 + 2] * gvi + r2 * gri) * Cv);
                }
            }
        }
    }
}

// -------- fused node kernel --------
// smem float offsets (total 92160 B -> 2 CTAs/SM)
#define NO_W2  0                 // 64*128 = 8192
#define NO_U   8192              // 128*68 = 8704
#define NO_STG 16896             // 6144
#define NODE_SMEM_FLOATS 23040

__global__ void __launch_bounds__(NTH, 2) node_kernel(
    float* __restrict__ s, float* __restrict__ v,
    const float* __restrict__ Wn1, const float* __restrict__ bn1,
    const float* __restrict__ Wn2, const float* __restrict__ bn2)
{
    extern __shared__ float sm[];
    float* Ws2 = sm + NO_W2;
    float* Us  = sm + NO_U;
    float* Stg = sm + NO_STG;

    const int tid = threadIdx.x;
    const int n0  = blockIdx.x * 128;

    for (int i = tid; i < HID * SDIM; i += NTH) Ws2[i] = Wn2[i];

    const int jt = tid & 15, et = tid >> 4;
    const int j0 = jt * 4,  nb = et * 8;
    const int xn = tid & 127;
    const int xk = (tid >> 7) * 8;
    int xcl = n0 + xn; if (xcl > NNODE - 1) xcl = NNODE - 1;
    const long xrow = (long)xcl;
    const int wrow = tid >> 4;
    const int wcol = (tid & 15) * 4;

    // ---------- GEMM-n1: [s|s_agg](128x256) @ Wn1(256x64) ----------
    u64 accp[4][4];
#pragma unroll
    for (int i = 0; i < 4; i++)
#pragma unroll
        for (int u = 0; u < 4; u++) accp[i][u] = 0ull;

    float4 q0, q1, p0, p1, wq, wp;
    {
        const float* rowp = (xk < SDIM) ? (s + xrow * SDIM + xk)
                                        : (g_sagg + xrow * SDIM + (xk - SDIM));
        q0 = *(const float4*)rowp;
        q1 = *(const float4*)(rowp + 4);
        wq = *(const float4*)&Wn1[wrow * HID + wcol];
        float* Xb = Stg;
        float* Wb = Stg + 2048;
        Xb[(xk + 0) * 128 + xn] = q0.x;
        Xb[(xk + 1) * 128 + xn] = q0.y;
        Xb[(xk + 2) * 128 + xn] = q0.z;
        Xb[(xk + 3) * 128 + xn] = q0.w;
        Xb[(xk + 4) * 128 + xn] = q1.x;
        Xb[(xk + 5) * 128 + xn] = q1.y;
        Xb[(xk + 6) * 128 + xn] = q1.z;
        Xb[(xk + 7) * 128 + xn] = q1.w;
        *(float4*)&Wb[wrow * HID + wcol] = wq;
    }
    for (int kc = 0; kc < 16; kc++) {
        const float* Xc = Stg + (kc & 1) * 3072;
        const float* Wc = Xc + 2048;
        if (kc < 15) {
            int kg = (kc + 1) * 16 + xk;
            const float* rowp = (kg < SDIM) ? (s + xrow * SDIM + kg)
                                            : (g_sagg + xrow * SDIM + (kg - SDIM));
            p0 = *(const float4*)rowp;
            p1 = *(const float4*)(rowp + 4);
            wp = *(const float4*)&Wn1[((kc + 1) * 16 + wrow) * HID + wcol];
        }
        __syncthreads();
#pragma unroll
        for (int kk = 0; kk < 16; kk++) {
            float4 bv = *(const float4*)&Wc[kk * HID + j0];
            u64 bp0 = pack2(bv.x), bp1 = pack2(bv.y), bp2 = pack2(bv.z), bp3 = pack2(bv.w);
            ulonglong2 A0 = *(const ulonglong2*)&Xc[kk * 128 + nb];
            ulonglong2 A1 = *(const ulonglong2*)&Xc[kk * 128 + nb + 4];
            u64 ap[4] = {A0.x, A0.y, A1.x, A1.y};
#pragma unroll
            for (int ip = 0; ip < 4; ip++) {
                fma2(accp[ip][0], ap[ip], bp0);
                fma2(accp[ip][1], ap[ip], bp1);
                fma2(accp[ip][2], ap[ip], bp2);
                fma2(accp[ip][3], ap[ip], bp3);
            }
        }
        if (kc < 15) {
            float* Xn = Stg + ((kc + 1) & 1) * 3072;
            float* Wn = Xn + 2048;
            Xn[(xk + 0) * 128 + xn] = p0.x;
            Xn[(xk + 1) * 128 + xn] = p0.y;
            Xn[(xk + 2) * 128 + xn] = p0.z;
            Xn[(xk + 3) * 128 + xn] = p0.w;
            Xn[(xk + 4) * 128 + xn] = p1.x;
            Xn[(xk + 5) * 128 + xn] = p1.y;
            Xn[(xk + 6) * 128 + xn] = p1.z;
            Xn[(xk + 7) * 128 + xn] = p1.w;
            *(float4*)&Wn[wrow * HID + wcol] = wp;
        }
    }
    {
        float4 bbv = *(const float4*)&bn1[j0];
        float bb[4] = {bbv.x, bbv.y, bbv.z, bbv.w};
#pragma unroll
        for (int ip = 0; ip < 4; ip++) {
            float2 f[4];
#pragma unroll
            for (int u = 0; u < 4; u++) f[u] = u2f(accp[ip][u]);
            float4 o0, o1;
            o0.x = silu(f[0].x + bb[0]);
            o0.y = silu(f[1].x + bb[1]);
            o0.z = silu(f[2].x + bb[2]);
            o0.w = silu(f[3].x + bb[3]);
            o1.x = silu(f[0].y + bb[0]);
            o1.y = silu(f[1].y + bb[1]);
            o1.z = silu(f[2].y + bb[2]);
            o1.w = silu(f[3].y + bb[3]);
            *(float4*)&Us[(nb + 2 * ip) * 68 + j0]     = o0;
            *(float4*)&Us[(nb + 2 * ip + 1) * 68 + j0] = o1;
        }
    }
    __syncthreads();

    // ---------- GEMM-n2: U(128x64) @ Wn2(64x128), k-paired; s += out + bn2 ----------
    const int j3 = jt * 8;
    u64 acc3p[8][4];
#pragma unroll
    for (int i = 0; i < 8; i++)
#pragma unroll
        for (int u = 0; u < 4; u++) acc3p[i][u] = 0ull;
#pragma unroll 2
    for (int kq = 0; kq < 32; kq++) {
        ulonglong2 B00 = *(const ulonglong2*)&Ws2[(2 * kq) * SDIM + j3];
        ulonglong2 B01 = *(const ulonglong2*)&Ws2[(2 * kq) * SDIM + j3 + 4];
        ulonglong2 B10 = *(const ulonglong2*)&Ws2[(2 * kq + 1) * SDIM + j3];
        ulonglong2 B11 = *(const ulonglong2*)&Ws2[(2 * kq + 1) * SDIM + j3 + 4];
#pragma unroll
        for (int i = 0; i < 8; i++) {
            float2 a2 = *(const float2*)&Us[(nb + i) * 68 + 2 * kq];
            u64 ap0 = pack2(a2.x), ap1 = pack2(a2.y);
            fma2(acc3p[i][0], ap0, B00.x);
            fma2(acc3p[i][1], ap0, B00.y);
            fma2(acc3p[i][2], ap0, B01.x);
            fma2(acc3p[i][3], ap0, B01.y);
            fma2(acc3p[i][0], ap1, B10.x);
            fma2(acc3p[i][1], ap1, B10.y);
            fma2(acc3p[i][2], ap1, B11.x);
            fma2(acc3p[i][3], ap1, B11.y);
        }
    }
    {
        float bb2[8];
#pragma unroll
        for (int u = 0; u < 8; u++) bb2[u] = bn2[j3 + u];
#pragma unroll
        for (int i = 0; i < 8; i++) {
            int n = n0 + nb + i;
            if (n < NNODE) {
                float* sp = s + (long)n * SDIM + j3;
                float4 v0 = *(float4*)&sp[0];
                float4 v1 = *(float4*)&sp[4];
                float2 f0 = u2f(acc3p[i][0]), f1 = u2f(acc3p[i][1]);
                float2 f2 = u2f(acc3p[i][2]), f3 = u2f(acc3p[i][3]);
                v0.x += f0.x + bb2[0]; v0.y += f0.y + bb2[1];
                v0.z += f1.x + bb2[2]; v0.w += f1.y + bb2[3];
                v1.x += f2.x + bb2[4]; v1.y += f2.y + bb2[5];
                v1.z += f3.x + bb2[6]; v1.w += f3.y + bb2[7];
                *(float4*)&sp[0] = v0;
                *(float4*)&sp[4] = v1;
            }
        }
    }
    // v += v_agg * inv_cnt
    if (tid < 128) {
        int n = n0 + tid;
        if (n < NNODE) {
            float ic = 1.0f / fmaxf(g_cnt[n], 1.0f);
            float* vp = v + (long)n * 9;
            const float* vap = g_vagg + (long)n * 9;
#pragma unroll
            for (int q = 0; q < 9; q++)
                vp[q] += vap[q] * ic;
        }
    }
}

// -------- launch --------
extern "C" void kernel_launch(void* const* d_in, const int* in_sizes, int n_in,
                              void* d_out, int out_size)
{
    const float* s_in = (const float*)d_in[0];
    const float* v_in = (const float*)d_in[1];
    const int*   ei   = (const int*)d_in[2];
    const float* dvec = (const float*)d_in[3];
    const float* r    = (const float*)d_in[4];
    const float* W1   = (const float*)d_in[5];
    const float* b1   = (const float*)d_in[6];
    const float* W2   = (const float*)d_in[7];
    const float* b2   = (const float*)d_in[8];
    const float* W3   = (const float*)d_in[9];
    const float* b3   = (const float*)d_in[10];
    const float* Wn1  = (const float*)d_in[11];
    const float* bn1  = (const float*)d_in[12];
    const float* Wn2  = (const float*)d_in[13];
    const float* bn2  = (const float*)d_in[14];

    float* s = (float*)d_out;
    float* v = s + (size_t)NNODE * SDIM;

    cudaFuncSetAttribute(edge_kernel, cudaFuncAttributeMaxDynamicSharedMemorySize,
                         EDGE_SMEM_FLOATS * 4);
    cudaFuncSetAttribute(node_kernel, cudaFuncAttributeMaxDynamicSharedMemorySize,
                         NODE_SMEM_FLOATS * 4);

    void *p_cnt, *p_sagg, *p_vagg;
    cudaGetSymbolAddress(&p_cnt, g_cnt);
    cudaGetSymbolAddress(&p_sagg, g_sagg);
    cudaGetSymbolAddress(&p_vagg, g_vagg);

    cudaMemcpyAsync(s, s_in, sizeof(float) * NNODE * SDIM, cudaMemcpyDeviceToDevice, 0);
    cudaMemcpyAsync(v, v_in, sizeof(float) * NNODE * 9, cudaMemcpyDeviceToDevice, 0);
    cudaMemsetAsync(p_cnt, 0, sizeof(float) * NNODE, 0);
    init_kernel<<<(NEDGE + 255) / 256, 256>>>(ei);

    for (int l = 0; l < NLAYER; l++) {
        cudaMemsetAsync(p_sagg, 0, sizeof(float) * NNODE * SDIM, 0);
        cudaMemsetAsync(p_vagg, 0, sizeof(float) * NNODE * 9, 0);
        edge_kernel<<<(NEDGE + TEB - 1) / TEB, NTH, EDGE_SMEM_FLOATS * 4>>>(
            s, v, ei, dvec, r,
            W1 + (size_t)l * K1DIM * HID, b1 + (size_t)l * HID,
            W2 + (size_t)l * HID * HID,   b2 + (size_t)l * HID,
            W3 + (size_t)l * HID * M3DIM, b3 + (size_t)l * M3DIM);
        node_kernel<<<(NNODE + 127) / 128, NTH, NODE_SMEM_FLOATS * 4>>>(
            s, v,
            Wn1 + (size_t)l * 2 * SDIM * HID, bn1 + (size_t)l * HID,
            Wn2 + (size_t)l * HID * SDIM,     bn2 + (size_t)l * SDIM);
    }
}

// round 10
// speedup vs baseline: 2.2535x; 1.4188x over previous
#include <cuda_runtime.h>
#include <math.h>

#define NNODE 50000
#define NEDGE 500000
#define SDIM 128
#define HID 64
#define NLAYER 4
#define M3DIM 134     // SD + 2*VD
#define K1DIM 257     // 2*SD + 1
#define TEB 128       // edges per block
#define NTH 256

typedef unsigned long long u64;

// -------- scratch (no cudaMalloc allowed) --------
__device__ float g_sagg[NNODE * SDIM];
__device__ float g_vagg[NNODE * 9];
__device__ float g_cnt[NNODE];
__device__ float g_PQ[NNODE * 128];   // per-layer node projections: [P(64) | Q(64)]

__device__ __forceinline__ float silu(float x) {
    return x / (1.0f + __expf(-x));
}
// packed f32x2 helpers
__device__ __forceinline__ u64 pack2(float x) {
    u64 r; asm("mov.b64 %0, {%1, %1};" : "=l"(r) : "f"(x)); return r;
}
__device__ __forceinline__ void fma2(u64& d, u64 a, u64 b) {
    asm("fma.rn.f32x2 %0, %1, %2, %0;" : "+l"(d) : "l"(a), "l"(b));
}
__device__ __forceinline__ float2 u2f(u64 x) {
    float2 f; asm("mov.b64 {%0, %1}, %2;" : "=f"(f.x), "=f"(f.y) : "l"(x)); return f;
}
// vectorized global reduction (sm_90+)
__device__ __forceinline__ void red_add_v4(float* p, float a, float b, float c, float d) {
    asm volatile("red.global.add.v4.f32 [%0], {%1, %2, %3, %4};"
                 :: "l"(p), "f"(a), "f"(b), "f"(c), "f"(d) : "memory");
}

// -------- in-degree counts --------
__global__ void init_kernel(const int* __restrict__ ei) {
    int e = blockIdx.x * blockDim.x + threadIdx.x;
    if (e < NEDGE) atomicAdd(&g_cnt[ei[e]], 1.0f);
}

// -------- per-layer node projection: g_PQ = [ s@W1[0:128] | s@W1[128:256] ] --------
// 128 nodes/block, 256 threads, thread tile 8 nodes x 8 cols, double-buffered k-chunks
#define PQ_SMEM_FLOATS 8192   // 2 bufs * (2048 X + 2048 W)

__global__ void __launch_bounds__(NTH, 2) pq_kernel(
    const float* __restrict__ s, const float* __restrict__ W1)
{
    extern __shared__ float sm[];
    const int tid = threadIdx.x;
    const int n0  = blockIdx.x * 128;

    const int jt = tid & 15, et = tid >> 4;
    const int j0 = jt * 8,  nb = et * 8;
    const int xn = tid & 127;
    const int xk = (tid >> 7) * 8;
    int xcl = n0 + xn; if (xcl > NNODE - 1) xcl = NNODE - 1;
    const long xrow = (long)xcl;
    const int wr = tid >> 4;          // 0..15 (k row in chunk)
    const int wc = (tid & 15) * 8;    // 0..120 (8 cols)

    u64 acc[4][8];
#pragma unroll
    for (int p = 0; p < 4; p++)
#pragma unroll
        for (int u = 0; u < 8; u++) acc[p][u] = 0ull;

    float4 q0, q1, p0, p1, wq0, wq1, wp0, wp1;
    {
        q0 = *(const float4*)(s + xrow * SDIM + xk);
        q1 = *(const float4*)(s + xrow * SDIM + xk + 4);
        const float* wsrc = (wc < 64) ? (W1 + wr * HID + wc)
                                      : (W1 + (128 + wr) * HID + (wc - 64));
        wq0 = *(const float4*)wsrc;
        wq1 = *(const float4*)(wsrc + 4);
        float* Xb = sm;
        float* Wb = sm + 2048;
        Xb[(xk + 0) * 128 + xn] = q0.x;
        Xb[(xk + 1) * 128 + xn] = q0.y;
        Xb[(xk + 2) * 128 + xn] = q0.z;
        Xb[(xk + 3) * 128 + xn] = q0.w;
        Xb[(xk + 4) * 128 + xn] = q1.x;
        Xb[(xk + 5) * 128 + xn] = q1.y;
        Xb[(xk + 6) * 128 + xn] = q1.z;
        Xb[(xk + 7) * 128 + xn] = q1.w;
        *(float4*)&Wb[wr * 128 + wc]     = wq0;
        *(float4*)&Wb[wr * 128 + wc + 4] = wq1;
    }
    for (int kc = 0; kc < 8; kc++) {
        const float* Xc = sm + (kc & 1) * 4096;
        const float* Wc = Xc + 2048;
        if (kc < 7) {
            int kg = (kc + 1) * 16;
            p0 = *(const float4*)(s + xrow * SDIM + kg + xk);
            p1 = *(const float4*)(s + xrow * SDIM + kg + xk + 4);
            const float* wsrc = (wc < 64) ? (W1 + (kg + wr) * HID + wc)
                                          : (W1 + (128 + kg + wr) * HID + (wc - 64));
            wp0 = *(const float4*)wsrc;
            wp1 = *(const float4*)(wsrc + 4);
        }
        __syncthreads();
#pragma unroll
        for (int kk = 0; kk < 16; kk++) {
            ulonglong2 A0 = *(const ulonglong2*)&Xc[kk * 128 + nb];
            ulonglong2 A1 = *(const ulonglong2*)&Xc[kk * 128 + nb + 4];
            u64 ap[4] = {A0.x, A0.y, A1.x, A1.y};
            float4 w0 = *(const float4*)&Wc[kk * 128 + j0];
            float4 w1v = *(const float4*)&Wc[kk * 128 + j0 + 4];
            u64 bp[8] = {pack2(w0.x), pack2(w0.y), pack2(w0.z), pack2(w0.w),
                         pack2(w1v.x), pack2(w1v.y), pack2(w1v.z), pack2(w1v.w)};
#pragma unroll
            for (int p = 0; p < 4; p++)
#pragma unroll
                for (int u = 0; u < 8; u++)
                    fma2(acc[p][u], ap[p], bp[u]);
        }
        if (kc < 7) {
            float* Xn = sm + ((kc + 1) & 1) * 4096;
            float* Wn = Xn + 2048;
            Xn[(xk + 0) * 128 + xn] = p0.x;
            Xn[(xk + 1) * 128 + xn] = p0.y;
            Xn[(xk + 2) * 128 + xn] = p0.z;
            Xn[(xk + 3) * 128 + xn] = p0.w;
            Xn[(xk + 4) * 128 + xn] = p1.x;
            Xn[(xk + 5) * 128 + xn] = p1.y;
            Xn[(xk + 6) * 128 + xn] = p1.z;
            Xn[(xk + 7) * 128 + xn] = p1.w;
            *(float4*)&Wn[wr * 128 + wc]     = wp0;
            *(float4*)&Wn[wr * 128 + wc + 4] = wp1;
        }
    }
    // store (no bias; bias folded into edge kernel)
#pragma unroll
    for (int p = 0; p < 4; p++) {
        float2 f[8];
#pragma unroll
        for (int u = 0; u < 8; u++) f[u] = u2f(acc[p][u]);
        int n = n0 + nb + 2 * p;
        if (n < NNODE) {
            float4 lo = {f[0].x, f[1].x, f[2].x, f[3].x};
            float4 hi = {f[4].x, f[5].x, f[6].x, f[7].x};
            *(float4*)&g_PQ[(long)n * 128 + j0]     = lo;
            *(float4*)&g_PQ[(long)n * 128 + j0 + 4] = hi;
        }
        if (n + 1 < NNODE) {
            float4 lo = {f[0].y, f[1].y, f[2].y, f[3].y};
            float4 hi = {f[4].y, f[5].y, f[6].y, f[7].y};
            *(float4*)&g_PQ[(long)(n + 1) * 128 + j0]     = lo;
            *(float4*)&g_PQ[(long)(n + 1) * 128 + j0 + 4] = hi;
        }
    }
}

// -------- fused edge kernel: gather P/Q -> silu -> GEMM2 -> GEMM3 -> scatter --------
// smem float offsets (total 91136 B -> 2 CTAs/SM)
#define EO_W2   0                // 64*64 = 4096
#define EO_H1   4096             // 128*68 = 8704
#define EO_H2   12800            // 128*68 = 8704
#define EO_SG   21504            // 768 (gv/gr staging)
#define EO_IDST 22272            // 128 ints
#define EO_ISRC 22400
#define EO_C    22528
#define EO_D    22656
#define EDGE_SMEM_FLOATS 22784

__global__ void __launch_bounds__(NTH, 2) edge_kernel(
    const float* __restrict__ s, const float* __restrict__ v,
    const int* __restrict__ ei, const float* __restrict__ dvec,
    const float* __restrict__ r,
    const float* __restrict__ W1, const float* __restrict__ b1,
    const float* __restrict__ W2, const float* __restrict__ b2,
    const float* __restrict__ W3, const float* __restrict__ b3)
{
    extern __shared__ float sm[];
    float* Ws2 = sm + EO_W2;
    float* Hs1 = sm + EO_H1;
    float* Hs2 = sm + EO_H2;
    float* sG  = sm + EO_SG;
    int*   sdst = (int*)(sm + EO_IDST);
    int*   ssrc = (int*)(sm + EO_ISRC);
    float* sC   = sm + EO_C;
    float* sd   = sm + EO_D;

    const int tid = threadIdx.x;
    const int e0  = blockIdx.x * TEB;

    // stage W2 + edge metadata
    for (int i = tid; i < HID * HID; i += NTH) Ws2[i] = W2[i];
    if (tid < TEB) {
        int e  = e0 + tid;
        int ec = (e < NEDGE) ? e : 0;
        sdst[tid] = ei[ec];
        ssrc[tid] = ei[NEDGE + ec];
        float dv = dvec[ec];
        float C = 0.5f * (cosf(0.62831853071795864769f * dv) + 1.0f);
        if (!(dv < 5.0f)) C = 0.0f;
        sC[tid] = (e < NEDGE) ? C : 0.0f;
        sd[tid] = dv;
    }
    __syncthreads();

    const int jt = tid & 15;       // 16 j-groups
    const int et = tid >> 4;       // 16 edge-groups
    const int j0 = jt * 4;
    const int eb = et * 8;

    // ---------- H1 = silu(P[dst] + Q[src] + d*w1last + b1) ----------
    {
        float4 wl  = *(const float4*)&W1[256 * HID + j0];
        float4 bbv = *(const float4*)&b1[j0];
#pragma unroll
        for (int i = 0; i < 8; i++) {
            int ee = eb + i;
            float4 pd = *(const float4*)&g_PQ[(long)sdst[ee] * 128 + j0];
            float4 qs = *(const float4*)&g_PQ[(long)ssrc[ee] * 128 + 64 + j0];
            float dd = sd[ee];
            float4 o;
            o.x = silu(pd.x + qs.x + dd * wl.x + bbv.x);
            o.y = silu(pd.y + qs.y + dd * wl.y + bbv.y);
            o.z = silu(pd.z + qs.z + dd * wl.z + bbv.z);
            o.w = silu(pd.w + qs.w + dd * wl.w + bbv.w);
            *(float4*)&Hs1[ee * 68 + j0] = o;
        }
    }
    __syncthreads();

    // ---------- GEMM2: H1(128x64) @ W2(64x64), col-packed, k-paired ----------
    u64 acc2p[8][2];
#pragma unroll
    for (int i = 0; i < 8; i++) { acc2p[i][0] = 0ull; acc2p[i][1] = 0ull; }
#pragma unroll 4
    for (int kq = 0; kq < 32; kq++) {
        ulonglong2 bv0 = *(const ulonglong2*)&Ws2[(2 * kq) * HID + j0];
        ulonglong2 bv1 = *(const ulonglong2*)&Ws2[(2 * kq + 1) * HID + j0];
#pragma unroll
        for (int i = 0; i < 8; i++) {
            float2 a2 = *(const float2*)&Hs1[(eb + i) * 68 + 2 * kq];
            u64 ap0 = pack2(a2.x), ap1 = pack2(a2.y);
            fma2(acc2p[i][0], ap0, bv0.x);
            fma2(acc2p[i][1], ap0, bv0.y);
            fma2(acc2p[i][0], ap1, bv1.x);
            fma2(acc2p[i][1], ap1, bv1.y);
        }
    }
    {
        float4 bbv = *(const float4*)&b2[j0];
        float bb[4] = {bbv.x, bbv.y, bbv.z, bbv.w};
#pragma unroll
        for (int i = 0; i < 8; i++) {
            float2 f0 = u2f(acc2p[i][0]), f1 = u2f(acc2p[i][1]);
            float4 o;
            o.x = silu(f0.x + bb[0]);
            o.y = silu(f0.y + bb[1]);
            o.z = silu(f1.x + bb[2]);
            o.w = silu(f1.y + bb[3]);
            *(float4*)&Hs2[(eb + i) * 68 + j0] = o;
        }
    }
    __syncthreads();

    // ---------- GEMM3: H2(128x64) @ W3(64x134), weights from gmem (L2), k-paired ----------
    const int j3 = jt * 8;      // first 128 cols (ms)
    u64 acc3p[8][4];
#pragma unroll
    for (int i = 0; i < 8; i++)
#pragma unroll
        for (int u = 0; u < 4; u++) acc3p[i][u] = 0ull;
#pragma unroll 2
    for (int kq = 0; kq < 32; kq++) {
        const float* wr0 = W3 + (2 * kq) * M3DIM + j3;       // 8B-aligned
        const float* wr1 = W3 + (2 * kq + 1) * M3DIM + j3;
        u64 b0[4], b1v[4];
#pragma unroll
        for (int u = 0; u < 4; u++) {
            b0[u]  = *(const u64*)(wr0 + 2 * u);
            b1v[u] = *(const u64*)(wr1 + 2 * u);
        }
#pragma unroll
        for (int i = 0; i < 8; i++) {
            float2 a2 = *(const float2*)&Hs2[(eb + i) * 68 + 2 * kq];
            u64 ap0 = pack2(a2.x), ap1 = pack2(a2.y);
            fma2(acc3p[i][0], ap0, b0[0]);
            fma2(acc3p[i][1], ap0, b0[1]);
            fma2(acc3p[i][2], ap0, b0[2]);
            fma2(acc3p[i][3], ap0, b0[3]);
            fma2(acc3p[i][0], ap1, b1v[0]);
            fma2(acc3p[i][1], ap1, b1v[1]);
            fma2(acc3p[i][2], ap1, b1v[2]);
            fma2(acc3p[i][3], ap1, b1v[3]);
        }
    }
    // scatter ms * C into s_agg (vector reductions)
    {
        float bb3[8];
#pragma unroll
        for (int u = 0; u < 8; u++) bb3[u] = b3[j3 + u];
#pragma unroll
        for (int i = 0; i < 8; i++) {
            int e = e0 + eb + i;
            if (e < NEDGE) {
                float Cv = sC[eb + i];
                float* sa = g_sagg + (long)sdst[eb + i] * SDIM + j3;
                float2 f0 = u2f(acc3p[i][0]), f1 = u2f(acc3p[i][1]);
                float2 f2 = u2f(acc3p[i][2]), f3 = u2f(acc3p[i][3]);
                red_add_v4(sa,
                           (f0.x + bb3[0]) * Cv, (f0.y + bb3[1]) * Cv,
                           (f1.x + bb3[2]) * Cv, (f1.y + bb3[3]) * Cv);
                red_add_v4(sa + 4,
                           (f2.x + bb3[4]) * Cv, (f2.y + bb3[5]) * Cv,
                           (f3.x + bb3[6]) * Cv, (f3.y + bb3[7]) * Cv);
            }
        }
    }

    // ---- gv/gr (cols 128..133): 256 threads compute, 128 scatter ----
    {
        const int te = tid & 127;
        const int th = tid >> 7;     // 0 -> gv, 1 -> gr
#pragma unroll
        for (int u = 0; u < 3; u++) {
            int col = 128 + th * 3 + u;
            float a = b3[col];
#pragma unroll 8
            for (int k = 0; k < HID; k++)
                a = fmaf(Hs2[te * 68 + k], W3[k * M3DIM + col], a);
            sG[te * 6 + th * 3 + u] = a;
        }
        __syncthreads();
        if (tid < TEB) {
            int e = e0 + tid;
            if (e < NEDGE) {
                float Cv = sC[tid];
                long srcn = ssrc[tid];
                long dstn = sdst[tid];
                float r0 = r[(long)e * 3 + 0];
                float r1 = r[(long)e * 3 + 1];
                float r2 = r[(long)e * 3 + 2];
                const float* vs = v + srcn * 9;
                float* va = g_vagg + dstn * 9;
#pragma unroll
                for (int i = 0; i < 3; i++) {
                    float gvi = sG[tid * 6 + i], gri = sG[tid * 6 + 3 + i];
                    atomicAdd(&va[i * 3 + 0], (vs[i * 3 + 0] * gvi + r0 * gri) * Cv);
                    atomicAdd(&va[i * 3 + 1], (vs[i * 3 + 1] * gvi + r1 * gri) * Cv);
                    atomicAdd(&va[i * 3 + 2], (vs[i * 3 + 2] * gvi + r2 * gri) * Cv);
                }
            }
        }
    }
}

// -------- fused node kernel --------
// smem float offsets (total 92160 B -> 2 CTAs/SM)
#define NO_W2  0                 // 64*128 = 8192
#define NO_U   8192              // 128*68 = 8704
#define NO_STG 16896             // 6144
#define NODE_SMEM_FLOATS 23040

__global__ void __launch_bounds__(NTH, 2) node_kernel(
    float* __restrict__ s, float* __restrict__ v,
    const float* __restrict__ Wn1, const float* __restrict__ bn1,
    const float* __restrict__ Wn2, const float* __restrict__ bn2)
{
    extern __shared__ float sm[];
    float* Ws2 = sm + NO_W2;
    float* Us  = sm + NO_U;
    float* Stg = sm + NO_STG;

    const int tid = threadIdx.x;
    const int n0  = blockIdx.x * 128;

    for (int i = tid; i < HID * SDIM; i += NTH) Ws2[i] = Wn2[i];

    const int jt = tid & 15, et = tid >> 4;
    const int j0 = jt * 4,  nb = et * 8;
    const int xn = tid & 127;
    const int xk = (tid >> 7) * 8;
    int xcl = n0 + xn; if (xcl > NNODE - 1) xcl = NNODE - 1;
    const long xrow = (long)xcl;
    const int wrow = tid >> 4;
    const int wcol = (tid & 15) * 4;

    // ---------- GEMM-n1: [s|s_agg](128x256) @ Wn1(256x64) ----------
    u64 accp[4][4];
#pragma unroll
    for (int i = 0; i < 4; i++)
#pragma unroll
        for (int u = 0; u < 4; u++) accp[i][u] = 0ull;

    float4 q0, q1, p0, p1, wq, wp;
    {
        const float* rowp = (xk < SDIM) ? (s + xrow * SDIM + xk)
                                        : (g_sagg + xrow * SDIM + (xk - SDIM));
        q0 = *(const float4*)rowp;
        q1 = *(const float4*)(rowp + 4);
        wq = *(const float4*)&Wn1[wrow * HID + wcol];
        float* Xb = Stg;
        float* Wb = Stg + 2048;
        Xb[(xk + 0) * 128 + xn] = q0.x;
        Xb[(xk + 1) * 128 + xn] = q0.y;
        Xb[(xk + 2) * 128 + xn] = q0.z;
        Xb[(xk + 3) * 128 + xn] = q0.w;
        Xb[(xk + 4) * 128 + xn] = q1.x;
        Xb[(xk + 5) * 128 + xn] = q1.y;
        Xb[(xk + 6) * 128 + xn] = q1.z;
        Xb[(xk + 7) * 128 + xn] = q1.w;
        *(float4*)&Wb[wrow * HID + wcol] = wq;
    }
    for (int kc = 0; kc < 16; kc++) {
        const float* Xc = Stg + (kc & 1) * 3072;
        const float* Wc = Xc + 2048;
        if (kc < 15) {
            int kg = (kc + 1) * 16 + xk;
            const float* rowp = (kg < SDIM) ? (s + xrow * SDIM + kg)
                                            : (g_sagg + xrow * SDIM + (kg - SDIM));
            p0 = *(const float4*)rowp;
            p1 = *(const float4*)(rowp + 4);
            wp = *(const float4*)&Wn1[((kc + 1) * 16 + wrow) * HID + wcol];
        }
        __syncthreads();
#pragma unroll
        for (int kk = 0; kk < 16; kk++) {
            float4 bv = *(const float4*)&Wc[kk * HID + j0];
            u64 bp0 = pack2(bv.x), bp1 = pack2(bv.y), bp2 = pack2(bv.z), bp3 = pack2(bv.w);
            ulonglong2 A0 = *(const ulonglong2*)&Xc[kk * 128 + nb];
            ulonglong2 A1 = *(const ulonglong2*)&Xc[kk * 128 + nb + 4];
            u64 ap[4] = {A0.x, A0.y, A1.x, A1.y};
#pragma unroll
            for (int ip = 0; ip < 4; ip++) {
                fma2(accp[ip][0], ap[ip], bp0);
                fma2(accp[ip][1], ap[ip], bp1);
                fma2(accp[ip][2], ap[ip], bp2);
                fma2(accp[ip][3], ap[ip], bp3);
            }
        }
        if (kc < 15) {
            float* Xn = Stg + ((kc + 1) & 1) * 3072;
            float* Wn = Xn + 2048;
            Xn[(xk + 0) * 128 + xn] = p0.x;
            Xn[(xk + 1) * 128 + xn] = p0.y;
            Xn[(xk + 2) * 128 + xn] = p0.z;
            Xn[(xk + 3) * 128 + xn] = p0.w;
            Xn[(xk + 4) * 128 + xn] = p1.x;
            Xn[(xk + 5) * 128 + xn] = p1.y;
            Xn[(xk + 6) * 128 + xn] = p1.z;
            Xn[(xk + 7) * 128 + xn] = p1.w;
            *(float4*)&Wn[wrow * HID + wcol] = wp;
        }
    }
    {
        float4 bbv = *(const float4*)&bn1[j0];
        float bb[4] = {bbv.x, bbv.y, bbv.z, bbv.w};
#pragma unroll
        for (int ip = 0; ip < 4; ip++) {
            float2 f[4];
#pragma unroll
            for (int u = 0; u < 4; u++) f[u] = u2f(accp[ip][u]);
            float4 o0, o1;
            o0.x = silu(f[0].x + bb[0]);
            o0.y = silu(f[1].x + bb[1]);
            o0.z = silu(f[2].x + bb[2]);
            o0.w = silu(f[3].x + bb[3]);
            o1.x = silu(f[0].y + bb[0]);
            o1.y = silu(f[1].y + bb[1]);
            o1.z = silu(f[2].y + bb[2]);
            o1.w = silu(f[3].y + bb[3]);
            *(float4*)&Us[(nb + 2 * ip) * 68 + j0]     = o0;
            *(float4*)&Us[(nb + 2 * ip + 1) * 68 + j0] = o1;
        }
    }
    __syncthreads();

    // ---------- GEMM-n2: U(128x64) @ Wn2(64x128), k-paired; s += out + bn2 ----------
    const int j3 = jt * 8;
    u64 acc3p[8][4];
#pragma unroll
    for (int i = 0; i < 8; i++)
#pragma unroll
        for (int u = 0; u < 4; u++) acc3p[i][u] = 0ull;
#pragma unroll 2
    for (int kq = 0; kq < 32; kq++) {
        ulonglong2 B00 = *(const ulonglong2*)&Ws2[(2 * kq) * SDIM + j3];
        ulonglong2 B01 = *(const ulonglong2*)&Ws2[(2 * kq) * SDIM + j3 + 4];
        ulonglong2 B10 = *(const ulonglong2*)&Ws2[(2 * kq + 1) * SDIM + j3];
        ulonglong2 B11 = *(const ulonglong2*)&Ws2[(2 * kq + 1) * SDIM + j3 + 4];
#pragma unroll
        for (int i = 0; i < 8; i++) {
            float2 a2 = *(const float2*)&Us[(nb + i) * 68 + 2 * kq];
            u64 ap0 = pack2(a2.x), ap1 = pack2(a2.y);
            fma2(acc3p[i][0], ap0, B00.x);
            fma2(acc3p[i][1], ap0, B00.y);
            fma2(acc3p[i][2], ap0, B01.x);
            fma2(acc3p[i][3], ap0, B01.y);
            fma2(acc3p[i][0], ap1, B10.x);
            fma2(acc3p[i][1], ap1, B10.y);
            fma2(acc3p[i][2], ap1, B11.x);
            fma2(acc3p[i][3], ap1, B11.y);
        }
    }
    {
        float bb2[8];
#pragma unroll
        for (int u = 0; u < 8; u++) bb2[u] = bn2[j3 + u];
#pragma unroll
        for (int i = 0; i < 8; i++) {
            int n = n0 + nb + i;
            if (n < NNODE) {
                float* sp = s + (long)n * SDIM + j3;
                float4 v0 = *(float4*)&sp[0];
                float4 v1 = *(float4*)&sp[4];
                float2 f0 = u2f(acc3p[i][0]), f1 = u2f(acc3p[i][1]);
                float2 f2 = u2f(acc3p[i][2]), f3 = u2f(acc3p[i][3]);
                v0.x += f0.x + bb2[0]; v0.y += f0.y + bb2[1];
                v0.z += f1.x + bb2[2]; v0.w += f1.y + bb2[3];
                v1.x += f2.x + bb2[4]; v1.y += f2.y + bb2[5];
                v1.z += f3.x + bb2[6]; v1.w += f3.y + bb2[7];
                *(float4*)&sp[0] = v0;
                *(float4*)&sp[4] = v1;
            }
        }
    }
    // v += v_agg * inv_cnt
    if (tid < 128) {
        int n = n0 + tid;
        if (n < NNODE) {
            float ic = 1.0f / fmaxf(g_cnt[n], 1.0f);
            float* vp = v + (long)n * 9;
            const float* vap = g_vagg + (long)n * 9;
#pragma unroll
            for (int q = 0; q < 9; q++)
                vp[q] += vap[q] * ic;
        }
    }
}

// -------- launch --------
extern "C" void kernel_launch(void* const* d_in, const int* in_sizes, int n_in,
                              void* d_out, int out_size)
{
    const float* s_in = (const float*)d_in[0];
    const float* v_in = (const float*)d_in[1];
    const int*   ei   = (const int*)d_in[2];
    const float* dvec = (const float*)d_in[3];
    const float* r    = (const float*)d_in[4];
    const float* W1   = (const float*)d_in[5];
    const float* b1   = (const float*)d_in[6];
    const float* W2   = (const float*)d_in[7];
    const float* b2   = (const float*)d_in[8];
    const float* W3   = (const float*)d_in[9];
    const float* b3   = (const float*)d_in[10];
    const float* Wn1  = (const float*)d_in[11];
    const float* bn1  = (const float*)d_in[12];
    const float* Wn2  = (const float*)d_in[13];
    const float* bn2  = (const float*)d_in[14];

    float* s = (float*)d_out;
    float* v = s + (size_t)NNODE * SDIM;

    cudaFuncSetAttribute(edge_kernel, cudaFuncAttributeMaxDynamicSharedMemorySize,
                         EDGE_SMEM_FLOATS * 4);
    cudaFuncSetAttribute(node_kernel, cudaFuncAttributeMaxDynamicSharedMemorySize,
                         NODE_SMEM_FLOATS * 4);
    cudaFuncSetAttribute(pq_kernel, cudaFuncAttributeMaxDynamicSharedMemorySize,
                         PQ_SMEM_FLOATS * 4);

    void *p_cnt, *p_sagg, *p_vagg;
    cudaGetSymbolAddress(&p_cnt, g_cnt);
    cudaGetSymbolAddress(&p_sagg, g_sagg);
    cudaGetSymbolAddress(&p_vagg, g_vagg);

    cudaMemcpyAsync(s, s_in, sizeof(float) * NNODE * SDIM, cudaMemcpyDeviceToDevice, 0);
    cudaMemcpyAsync(v, v_in, sizeof(float) * NNODE * 9, cudaMemcpyDeviceToDevice, 0);
    cudaMemsetAsync(p_cnt, 0, sizeof(float) * NNODE, 0);
    init_kernel<<<(NEDGE + 255) / 256, 256>>>(ei);

    const int nblk = (NNODE + 127) / 128;
    for (int l = 0; l < NLAYER; l++) {
        cudaMemsetAsync(p_sagg, 0, sizeof(float) * NNODE * SDIM, 0);
        cudaMemsetAsync(p_vagg, 0, sizeof(float) * NNODE * 9, 0);
        pq_kernel<<<nblk, NTH, PQ_SMEM_FLOATS * 4>>>(s, W1 + (size_t)l * K1DIM * HID);
        edge_kernel<<<(NEDGE + TEB - 1) / TEB, NTH, EDGE_SMEM_FLOATS * 4>>>(
            s, v, ei, dvec, r,
            W1 + (size_t)l * K1DIM * HID, b1 + (size_t)l * HID,
            W2 + (size_t)l * HID * HID,   b2 + (size_t)l * HID,
            W3 + (size_t)l * HID * M3DIM, b3 + (size_t)l * M3DIM);
        node_kernel<<<nblk, NTH, NODE_SMEM_FLOATS * 4>>>(
            s, v,
            Wn1 + (size_t)l * 2 * SDIM * HID, bn1 + (size_t)l * HID,
            Wn2 + (size_t)l * HID * SDIM,     bn2 + (size_t)l * SDIM);
    }
}

// round 17
// speedup vs baseline: 2.3598x; 1.0472x over previous
#include <cuda_runtime.h>
#include <math.h>

#define NNODE 50000
#define NEDGE 500000
#define SDIM 128
#define HID 64
#define NLAYER 4
#define M3DIM 134     // SD + 2*VD
#define K1DIM 257     // 2*SD + 1
#define TEB 128       // edges per block
#define NTH 256

typedef unsigned long long u64;

// -------- scratch (no cudaMalloc allowed) --------
__device__ float g_sagg[NNODE * SDIM];
__device__ float g_vagg[NNODE * 9];
__device__ float g_cnt[NNODE];
__device__ float g_PQ[NNODE * 128];   // per-layer node projections: [P(64) | Q(64)]

__device__ __forceinline__ float silu(float x) {
    return x / (1.0f + __expf(-x));
}
// packed f32x2 helpers
__device__ __forceinline__ u64 pack2(float x) {
    u64 r; asm("mov.b64 %0, {%1, %1};" : "=l"(r) : "f"(x)); return r;
}
__device__ __forceinline__ void fma2(u64& d, u64 a, u64 b) {
    asm("fma.rn.f32x2 %0, %1, %2, %0;" : "+l"(d) : "l"(a), "l"(b));
}
__device__ __forceinline__ float2 u2f(u64 x) {
    float2 f; asm("mov.b64 {%0, %1}, %2;" : "=f"(f.x), "=f"(f.y) : "l"(x)); return f;
}
// vectorized global reduction (sm_90+)
__device__ __forceinline__ void red_add_v4(float* p, float a, float b, float c, float d) {
    asm volatile("red.global.add.v4.f32 [%0], {%1, %2, %3, %4};"
                 :: "l"(p), "f"(a), "f"(b), "f"(c), "f"(d) : "memory");
}

// -------- in-degree counts --------
__global__ void init_kernel(const int* __restrict__ ei) {
    int e = blockIdx.x * blockDim.x + threadIdx.x;
    if (e < NEDGE) atomicAdd(&g_cnt[ei[e]], 1.0f);
}

// -------- per-layer node projection: g_PQ = [ s@W1[0:128] | s@W1[128:256] ] --------
#define PQ_SMEM_FLOATS 8192   // 2 bufs * (2048 X + 2048 W)

__global__ void __launch_bounds__(NTH, 2) pq_kernel(
    const float* __restrict__ s, const float* __restrict__ W1)
{
    extern __shared__ float sm[];
    const int tid = threadIdx.x;
    const int n0  = blockIdx.x * 128;

    const int jt = tid & 15, et = tid >> 4;
    const int j0 = jt * 8,  nb = et * 8;
    const int xn = tid & 127;
    const int xk = (tid >> 7) * 8;
    int xcl = n0 + xn; if (xcl > NNODE - 1) xcl = NNODE - 1;
    const long xrow = (long)xcl;
    const int wr = tid >> 4;          // 0..15 (k row in chunk)
    const int wc = (tid & 15) * 8;    // 0..120 (8 cols)

    u64 acc[4][8];
#pragma unroll
    for (int p = 0; p < 4; p++)
#pragma unroll
        for (int u = 0; u < 8; u++) acc[p][u] = 0ull;

    float4 q0, q1, p0, p1, wq0, wq1, wp0, wp1;
    {
        q0 = *(const float4*)(s + xrow * SDIM + xk);
        q1 = *(const float4*)(s + xrow * SDIM + xk + 4);
        const float* wsrc = (wc < 64) ? (W1 + wr * HID + wc)
                                      : (W1 + (128 + wr) * HID + (wc - 64));
        wq0 = *(const float4*)wsrc;
        wq1 = *(const float4*)(wsrc + 4);
        float* Xb = sm;
        float* Wb = sm + 2048;
        Xb[(xk + 0) * 128 + xn] = q0.x;
        Xb[(xk + 1) * 128 + xn] = q0.y;
        Xb[(xk + 2) * 128 + xn] = q0.z;
        Xb[(xk + 3) * 128 + xn] = q0.w;
        Xb[(xk + 4) * 128 + xn] = q1.x;
        Xb[(xk + 5) * 128 + xn] = q1.y;
        Xb[(xk + 6) * 128 + xn] = q1.z;
        Xb[(xk + 7) * 128 + xn] = q1.w;
        *(float4*)&Wb[wr * 128 + wc]     = wq0;
        *(float4*)&Wb[wr * 128 + wc + 4] = wq1;
    }
    for (int kc = 0; kc < 8; kc++) {
        const float* Xc = sm + (kc & 1) * 4096;
        const float* Wc = Xc + 2048;
        if (kc < 7) {
            int kg = (kc + 1) * 16;
            p0 = *(const float4*)(s + xrow * SDIM + kg + xk);
            p1 = *(const float4*)(s + xrow * SDIM + kg + xk + 4);
            const float* wsrc = (wc < 64) ? (W1 + (kg + wr) * HID + wc)
                                          : (W1 + (128 + kg + wr) * HID + (wc - 64));
            wp0 = *(const float4*)wsrc;
            wp1 = *(const float4*)(wsrc + 4);
        }
        __syncthreads();
#pragma unroll
        for (int kk = 0; kk < 16; kk++) {
            ulonglong2 A0 = *(const ulonglong2*)&Xc[kk * 128 + nb];
            ulonglong2 A1 = *(const ulonglong2*)&Xc[kk * 128 + nb + 4];
            u64 ap[4] = {A0.x, A0.y, A1.x, A1.y};
            float4 w0 = *(const float4*)&Wc[kk * 128 + j0];
            float4 w1v = *(const float4*)&Wc[kk * 128 + j0 + 4];
            u64 bp[8] = {pack2(w0.x), pack2(w0.y), pack2(w0.z), pack2(w0.w),
                         pack2(w1v.x), pack2(w1v.y), pack2(w1v.z), pack2(w1v.w)};
#pragma unroll
            for (int p = 0; p < 4; p++)
#pragma unroll
                for (int u = 0; u < 8; u++)
                    fma2(acc[p][u], ap[p], bp[u]);
        }
        if (kc < 7) {
            float* Xn = sm + ((kc + 1) & 1) * 4096;
            float* Wn = Xn + 2048;
            Xn[(xk + 0) * 128 + xn] = p0.x;
            Xn[(xk + 1) * 128 + xn] = p0.y;
            Xn[(xk + 2) * 128 + xn] = p0.z;
            Xn[(xk + 3) * 128 + xn] = p0.w;
            Xn[(xk + 4) * 128 + xn] = p1.x;
            Xn[(xk + 5) * 128 + xn] = p1.y;
            Xn[(xk + 6) * 128 + xn] = p1.z;
            Xn[(xk + 7) * 128 + xn] = p1.w;
            *(float4*)&Wn[wr * 128 + wc]     = wp0;
            *(float4*)&Wn[wr * 128 + wc + 4] = wp1;
        }
    }
#pragma unroll
    for (int p = 0; p < 4; p++) {
        float2 f[8];
#pragma unroll
        for (int u = 0; u < 8; u++) f[u] = u2f(acc[p][u]);
        int n = n0 + nb + 2 * p;
        if (n < NNODE) {
            float4 lo = {f[0].x, f[1].x, f[2].x, f[3].x};
            float4 hi = {f[4].x, f[5].x, f[6].x, f[7].x};
            *(float4*)&g_PQ[(long)n * 128 + j0]     = lo;
            *(float4*)&g_PQ[(long)n * 128 + j0 + 4] = hi;
        }
        if (n + 1 < NNODE) {
            float4 lo = {f[0].y, f[1].y, f[2].y, f[3].y};
            float4 hi = {f[4].y, f[5].y, f[6].y, f[7].y};
            *(float4*)&g_PQ[(long)(n + 1) * 128 + j0]     = lo;
            *(float4*)&g_PQ[(long)(n + 1) * 128 + j0 + 4] = hi;
        }
    }
}

// -------- fused edge kernel: gather P/Q -> silu -> GEMM2 -> GEMM3 -> scatter --------
// smem float offsets (total 92672 B -> 2 CTAs/SM)
#define EO_W2   0                // 64*64 = 4096
#define EO_H1   4096             // 128*68 = 8704
#define EO_H2   12800            // 128*68 = 8704
#define EO_W3T  21504            // 6*64 = 384 (tail cols of W3, transposed)
#define EO_SG   21888            // 768 (gv/gr staging)
#define EO_IDST 22656            // 128 ints
#define EO_ISRC 22784
#define EO_C    22912
#define EO_D    23040
#define EDGE_SMEM_FLOATS 23168

__global__ void __launch_bounds__(NTH, 2) edge_kernel(
    const float* __restrict__ s, const float* __restrict__ v,
    const int* __restrict__ ei, const float* __restrict__ dvec,
    const float* __restrict__ r,
    const float* __restrict__ W1, const float* __restrict__ b1,
    const float* __restrict__ W2, const float* __restrict__ b2,
    const float* __restrict__ W3, const float* __restrict__ b3)
{
    extern __shared__ float sm[];
    float* Ws2 = sm + EO_W2;
    float* Hs1 = sm + EO_H1;
    float* Hs2 = sm + EO_H2;
    float* W3t = sm + EO_W3T;
    float* sG  = sm + EO_SG;
    int*   sdst = (int*)(sm + EO_IDST);
    int*   ssrc = (int*)(sm + EO_ISRC);
    float* sC   = sm + EO_C;
    float* sd   = sm + EO_D;

    const int tid = threadIdx.x;
    const int e0  = blockIdx.x * TEB;

    // stage W2, W3 tail cols (transposed, FIXED: strided loop covers all 384), metadata
    for (int i = tid; i < HID * HID; i += NTH) Ws2[i] = W2[i];
    for (int i = tid; i < 6 * 64; i += NTH) {
        int c = i >> 6, k = i & 63;
        W3t[c * 64 + k] = W3[k * M3DIM + 128 + c];
    }
    if (tid < TEB) {
        int e  = e0 + tid;
        int ec = (e < NEDGE) ? e : 0;
        sdst[tid] = ei[ec];
        ssrc[tid] = ei[NEDGE + ec];
        float dv = dvec[ec];
        float C = 0.5f * (cosf(0.62831853071795864769f * dv) + 1.0f);
        if (!(dv < 5.0f)) C = 0.0f;
        sC[tid] = (e < NEDGE) ? C : 0.0f;
        sd[tid] = dv;
    }
    __syncthreads();

    const int jt = tid & 15;       // 16 j-groups
    const int et = tid >> 4;       // 16 edge-groups
    const int j0 = jt * 4;
    const int eb = et * 8;

    // ---------- H1 = silu(P[dst] + Q[src] + d*w1last + b1) ----------
    {
        float4 wl  = *(const float4*)&W1[256 * HID + j0];
        float4 bbv = *(const float4*)&b1[j0];
#pragma unroll
        for (int i = 0; i < 8; i++) {
            int ee = eb + i;
            float4 pd = *(const float4*)&g_PQ[(long)sdst[ee] * 128 + j0];
            float4 qs = *(const float4*)&g_PQ[(long)ssrc[ee] * 128 + 64 + j0];
            float dd = sd[ee];
            float4 o;
            o.x = silu(pd.x + qs.x + dd * wl.x + bbv.x);
            o.y = silu(pd.y + qs.y + dd * wl.y + bbv.y);
            o.z = silu(pd.z + qs.z + dd * wl.z + bbv.z);
            o.w = silu(pd.w + qs.w + dd * wl.w + bbv.w);
            *(float4*)&Hs1[ee * 68 + j0] = o;
        }
    }
    __syncthreads();

    // ---------- GEMM2: H1(128x64) @ W2(64x64), col-packed, k-paired ----------
    u64 acc2p[8][2];
#pragma unroll
    for (int i = 0; i < 8; i++) { acc2p[i][0] = 0ull; acc2p[i][1] = 0ull; }
#pragma unroll 4
    for (int kq = 0; kq < 32; kq++) {
        ulonglong2 bv0 = *(const ulonglong2*)&Ws2[(2 * kq) * HID + j0];
        ulonglong2 bv1 = *(const ulonglong2*)&Ws2[(2 * kq + 1) * HID + j0];
#pragma unroll
        for (int i = 0; i < 8; i++) {
            float2 a2 = *(const float2*)&Hs1[(eb + i) * 68 + 2 * kq];
            u64 ap0 = pack2(a2.x), ap1 = pack2(a2.y);
            fma2(acc2p[i][0], ap0, bv0.x);
            fma2(acc2p[i][1], ap0, bv0.y);
            fma2(acc2p[i][0], ap1, bv1.x);
            fma2(acc2p[i][1], ap1, bv1.y);
        }
    }
    {
        float4 bbv = *(const float4*)&b2[j0];
        float bb[4] = {bbv.x, bbv.y, bbv.z, bbv.w};
#pragma unroll
        for (int i = 0; i < 8; i++) {
            float2 f0 = u2f(acc2p[i][0]), f1 = u2f(acc2p[i][1]);
            float4 o;
            o.x = silu(f0.x + bb[0]);
            o.y = silu(f0.y + bb[1]);
            o.z = silu(f1.x + bb[2]);
            o.w = silu(f1.y + bb[3]);
            *(float4*)&Hs2[(eb + i) * 68 + j0] = o;
        }
    }
    __syncthreads();

    // ---------- GEMM3: H2(128x64) @ W3(64x134), weights from gmem (L2), k-paired ----------
    const int j3 = jt * 8;      // first 128 cols (ms)
    u64 acc3p[8][4];
#pragma unroll
    for (int i = 0; i < 8; i++)
#pragma unroll
        for (int u = 0; u < 4; u++) acc3p[i][u] = 0ull;
#pragma unroll 2
    for (int kq = 0; kq < 32; kq++) {
        const float* wr0 = W3 + (2 * kq) * M3DIM + j3;       // 8B-aligned
        const float* wr1 = W3 + (2 * kq + 1) * M3DIM + j3;
        u64 b0[4], b1v[4];
#pragma unroll
        for (int u = 0; u < 4; u++) {
            b0[u]  = *(const u64*)(wr0 + 2 * u);
            b1v[u] = *(const u64*)(wr1 + 2 * u);
        }
#pragma unroll
        for (int i = 0; i < 8; i++) {
            float2 a2 = *(const float2*)&Hs2[(eb + i) * 68 + 2 * kq];
            u64 ap0 = pack2(a2.x), ap1 = pack2(a2.y);
            fma2(acc3p[i][0], ap0, b0[0]);
            fma2(acc3p[i][1], ap0, b0[1]);
            fma2(acc3p[i][2], ap0, b0[2]);
            fma2(acc3p[i][3], ap0, b0[3]);
            fma2(acc3p[i][0], ap1, b1v[0]);
            fma2(acc3p[i][1], ap1, b1v[1]);
            fma2(acc3p[i][2], ap1, b1v[2]);
            fma2(acc3p[i][3], ap1, b1v[3]);
        }
    }
    // scatter ms * C into s_agg (vector reductions)
    {
        float bb3[8];
#pragma unroll
        for (int u = 0; u < 8; u++) bb3[u] = b3[j3 + u];
#pragma unroll
        for (int i = 0; i < 8; i++) {
            int e = e0 + eb + i;
            if (e < NEDGE) {
                float Cv = sC[eb + i];
                float* sa = g_sagg + (long)sdst[eb + i] * SDIM + j3;
                float2 f0 = u2f(acc3p[i][0]), f1 = u2f(acc3p[i][1]);
                float2 f2 = u2f(acc3p[i][2]), f3 = u2f(acc3p[i][3]);
                red_add_v4(sa,
                           (f0.x + bb3[0]) * Cv, (f0.y + bb3[1]) * Cv,
                           (f1.x + bb3[2]) * Cv, (f1.y + bb3[3]) * Cv);
                red_add_v4(sa + 4,
                           (f2.x + bb3[4]) * Cv, (f2.y + bb3[5]) * Cv,
                           (f3.x + bb3[6]) * Cv, (f3.y + bb3[7]) * Cv);
            }
        }
    }

    // ---- gv/gr (cols 128..133): k-paired smem tail; 256 compute, 128 scatter ----
    {
        const int te = tid & 127;
        const int th = tid >> 7;     // 0 -> cols 128..130, 1 -> cols 131..133
        u64 tacc[3] = {0ull, 0ull, 0ull};
        const float* arow = &Hs2[te * 68];
        const float* w0 = &W3t[(th * 3 + 0) * 64];
        const float* w1 = &W3t[(th * 3 + 1) * 64];
        const float* w2 = &W3t[(th * 3 + 2) * 64];
#pragma unroll 8
        for (int kq = 0; kq < 32; kq++) {
            u64 a2 = *(const u64*)(arow + 2 * kq);
            fma2(tacc[0], a2, *(const u64*)(w0 + 2 * kq));
            fma2(tacc[1], a2, *(const u64*)(w1 + 2 * kq));
            fma2(tacc[2], a2, *(const u64*)(w2 + 2 * kq));
        }
#pragma unroll
        for (int u = 0; u < 3; u++) {
            float2 f = u2f(tacc[u]);
            sG[te * 6 + th * 3 + u] = f.x + f.y + b3[128 + th * 3 + u];
        }
        __syncthreads();
        if (tid < TEB) {
            int e = e0 + tid;
            if (e < NEDGE) {
                float Cv = sC[tid];
                long srcn = ssrc[tid];
                long dstn = sdst[tid];
                float r0 = r[(long)e * 3 + 0];
                float r1 = r[(long)e * 3 + 1];
                float r2 = r[(long)e * 3 + 2];
                const float* vs = v + srcn * 9;
                float* va = g_vagg + dstn * 9;
#pragma unroll
                for (int i = 0; i < 3; i++) {
                    float gvi = sG[tid * 6 + i], gri = sG[tid * 6 + 3 + i];
                    atomicAdd(&va[i * 3 + 0], (vs[i * 3 + 0] * gvi + r0 * gri) * Cv);
                    atomicAdd(&va[i * 3 + 1], (vs[i * 3 + 1] * gvi + r1 * gri) * Cv);
                    atomicAdd(&va[i * 3 + 2], (vs[i * 3 + 2] * gvi + r2 * gri) * Cv);
                }
            }
        }
    }
}

// -------- fused node kernel: 32-wide k chunks, Wn2 from gmem --------
// smem float offsets (total 83968 B -> 2 CTAs/SM)
#define NO_U   0                 // 128*68 = 8704
#define NO_STG 8704              // 2 bufs * (4096 X + 2048 W) = 12288
#define NODE_SMEM_FLOATS 20992

__global__ void __launch_bounds__(NTH, 2) node_kernel(
    float* __restrict__ s, float* __restrict__ v,
    const float* __restrict__ Wn1, const float* __restrict__ bn1,
    const float* __restrict__ Wn2, const float* __restrict__ bn2)
{
    extern __shared__ float sm[];
    float* Us  = sm + NO_U;
    float* Stg = sm + NO_STG;

    const int tid = threadIdx.x;
    const int n0  = blockIdx.x * 128;

    const int jt = tid & 15, et = tid >> 4;
    const int j0 = jt * 4,  nb = et * 8;
    const int xn = tid & 127;
    const int xo = (tid >> 7) * 16;   // 0 or 16: k-offset within 32-chunk
    int xcl = n0 + xn; if (xcl > NNODE - 1) xcl = NNODE - 1;
    const long xrow = (long)xcl;
    const int wr = tid >> 3;          // 0..31 (k row in chunk)
    const int wc = (tid & 7) * 8;     // 0..56 (8 cols)

    // ---------- GEMM-n1: [s|s_agg](128x256) @ Wn1(256x64), 8 chunks of k=32 ----------
    u64 accp[4][4];
#pragma unroll
    for (int i = 0; i < 4; i++)
#pragma unroll
        for (int u = 0; u < 4; u++) accp[i][u] = 0ull;

    float4 q[4], p[4], wq0, wq1, wp0, wp1;
    {
        const float* rowp = s + xrow * SDIM + xo;   // chunk 0: always in s
#pragma unroll
        for (int j = 0; j < 4; j++) q[j] = *(const float4*)(rowp + 4 * j);
        wq0 = *(const float4*)&Wn1[wr * HID + wc];
        wq1 = *(const float4*)&Wn1[wr * HID + wc + 4];
        float* Xb = Stg;
        float* Wb = Stg + 4096;
#pragma unroll
        for (int j = 0; j < 4; j++) {
            Xb[(xo + 4 * j + 0) * 128 + xn] = q[j].x;
            Xb[(xo + 4 * j + 1) * 128 + xn] = q[j].y;
            Xb[(xo + 4 * j + 2) * 128 + xn] = q[j].z;
            Xb[(xo + 4 * j + 3) * 128 + xn] = q[j].w;
        }
        *(float4*)&Wb[wr * HID + wc]     = wq0;
        *(float4*)&Wb[wr * HID + wc + 4] = wq1;
    }
    for (int kc = 0; kc < 8; kc++) {
        const float* Xc = Stg + (kc & 1) * 6144;
        const float* Wc = Xc + 4096;
        if (kc < 7) {
            int kg = (kc + 1) * 32 + xo;
            const float* rowp = (kg < SDIM) ? (s + xrow * SDIM + kg)
                                            : (g_sagg + xrow * SDIM + (kg - SDIM));
#pragma unroll
            for (int j = 0; j < 4; j++) p[j] = *(const float4*)(rowp + 4 * j);
            wp0 = *(const float4*)&Wn1[((kc + 1) * 32 + wr) * HID + wc];
            wp1 = *(const float4*)&Wn1[((kc + 1) * 32 + wr) * HID + wc + 4];
        }
        __syncthreads();
#pragma unroll
        for (int kk = 0; kk < 32; kk++) {
            float4 bv = *(const float4*)&Wc[kk * HID + j0];
            u64 bp0 = pack2(bv.x), bp1 = pack2(bv.y), bp2 = pack2(bv.z), bp3 = pack2(bv.w);
            ulonglong2 A0 = *(const ulonglong2*)&Xc[kk * 128 + nb];
            ulonglong2 A1 = *(const ulonglong2*)&Xc[kk * 128 + nb + 4];
            u64 ap[4] = {A0.x, A0.y, A1.x, A1.y};
#pragma unroll
            for (int ip = 0; ip < 4; ip++) {
                fma2(accp[ip][0], ap[ip], bp0);
                fma2(accp[ip][1], ap[ip], bp1);
                fma2(accp[ip][2], ap[ip], bp2);
                fma2(accp[ip][3], ap[ip], bp3);
            }
        }
        if (kc < 7) {
            float* Xn = Stg + ((kc + 1) & 1) * 6144;
            float* Wn = Xn + 4096;
#pragma unroll
            for (int j = 0; j < 4; j++) {
                Xn[(xo + 4 * j + 0) * 128 + xn] = p[j].x;
                Xn[(xo + 4 * j + 1) * 128 + xn] = p[j].y;
                Xn[(xo + 4 * j + 2) * 128 + xn] = p[j].z;
                Xn[(xo + 4 * j + 3) * 128 + xn] = p[j].w;
            }
            *(float4*)&Wn[wr * HID + wc]     = wp0;
            *(float4*)&Wn[wr * HID + wc + 4] = wp1;
        }
    }
    {
        float4 bbv = *(const float4*)&bn1[j0];
        float bb[4] = {bbv.x, bbv.y, bbv.z, bbv.w};
#pragma unroll
        for (int ip = 0; ip < 4; ip++) {
            float2 f[4];
#pragma unroll
            for (int u = 0; u < 4; u++) f[u] = u2f(accp[ip][u]);
            float4 o0, o1;
            o0.x = silu(f[0].x + bb[0]);
            o0.y = silu(f[1].x + bb[1]);
            o0.z = silu(f[2].x + bb[2]);
            o0.w = silu(f[3].x + bb[3]);
            o1.x = silu(f[0].y + bb[0]);
            o1.y = silu(f[1].y + bb[1]);
            o1.z = silu(f[2].y + bb[2]);
            o1.w = silu(f[3].y + bb[3]);
            *(float4*)&Us[(nb + 2 * ip) * 68 + j0]     = o0;
            *(float4*)&Us[(nb + 2 * ip + 1) * 68 + j0] = o1;
        }
    }
    __syncthreads();

    // ---------- GEMM-n2: U(128x64) @ Wn2(64x128), weights from gmem; s += out + bn2 ----------
    const int j3 = jt * 8;
    u64 acc3p[8][4];
#pragma unroll
    for (int i = 0; i < 8; i++)
#pragma unroll
        for (int u = 0; u < 4; u++) acc3p[i][u] = 0ull;
#pragma unroll 2
    for (int kq = 0; kq < 32; kq++) {
        const float* wr0 = Wn2 + (2 * kq) * SDIM + j3;
        const float* wr1 = Wn2 + (2 * kq + 1) * SDIM + j3;
        u64 b0[4], b1v[4];
#pragma unroll
        for (int u = 0; u < 4; u++) {
            b0[u]  = *(const u64*)(wr0 + 2 * u);
            b1v[u] = *(const u64*)(wr1 + 2 * u);
        }
#pragma unroll
        for (int i = 0; i < 8; i++) {
            float2 a2 = *(const float2*)&Us[(nb + i) * 68 + 2 * kq];
            u64 ap0 = pack2(a2.x), ap1 = pack2(a2.y);
            fma2(acc3p[i][0], ap0, b0[0]);
            fma2(acc3p[i][1], ap0, b0[1]);
            fma2(acc3p[i][2], ap0, b0[2]);
            fma2(acc3p[i][3], ap0, b0[3]);
            fma2(acc3p[i][0], ap1, b1v[0]);
            fma2(acc3p[i][1], ap1, b1v[1]);
            fma2(acc3p[i][2], ap1, b1v[2]);
            fma2(acc3p[i][3], ap1, b1v[3]);
        }
    }
    {
        float bb2[8];
#pragma unroll
        for (int u = 0; u < 8; u++) bb2[u] = bn2[j3 + u];
#pragma unroll
        for (int i = 0; i < 8; i++) {
            int n = n0 + nb + i;
            if (n < NNODE) {
                float* sp = s + (long)n * SDIM + j3;
                float4 v0 = *(float4*)&sp[0];
                float4 v1 = *(float4*)&sp[4];
                float2 f0 = u2f(acc3p[i][0]), f1 = u2f(acc3p[i][1]);
                float2 f2 = u2f(acc3p[i][2]), f3 = u2f(acc3p[i][3]);
                v0.x += f0.x + bb2[0]; v0.y += f0.y + bb2[1];
                v0.z += f1.x + bb2[2]; v0.w += f1.y + bb2[3];
                v1.x += f2.x + bb2[4]; v1.y += f2.y + bb2[5];
                v1.z += f3.x + bb2[6]; v1.w += f3.y + bb2[7];
                *(float4*)&sp[0] = v0;
                *(float4*)&sp[4] = v1;
            }
        }
    }
    // v += v_agg * inv_cnt
    if (tid < 128) {
        int n = n0 + tid;
        if (n < NNODE) {
            float ic = 1.0f / fmaxf(g_cnt[n], 1.0f);
            float* vp = v + (long)n * 9;
            const float* vap = g_vagg + (long)n * 9;
#pragma unroll
            for (int q = 0; q < 9; q++)
                vp[q] += vap[q] * ic;
        }
    }
}

// -------- launch --------
extern "C" void kernel_launch(void* const* d_in, const int* in_sizes, int n_in,
                              void* d_out, int out_size)
{
    const float* s_in = (const float*)d_in[0];
    const float* v_in = (const float*)d_in[1];
    const int*   ei   = (const int*)d_in[2];
    const float* dvec = (const float*)d_in[3];
    const float* r    = (const float*)d_in[4];
    const float* W1   = (const float*)d_in[5];
    const float* b1   = (const float*)d_in[6];
    const float* W2   = (const float*)d_in[7];
    const float* b2   = (const float*)d_in[8];
    const float* W3   = (const float*)d_in[9];
    const float* b3   = (const float*)d_in[10];
    const float* Wn1  = (const float*)d_in[11];
    const float* bn1  = (const float*)d_in[12];
    const float* Wn2  = (const float*)d_in[13];
    const float* bn2  = (const float*)d_in[14];

    float* s = (float*)d_out;
    float* v = s + (size_t)NNODE * SDIM;

    cudaFuncSetAttribute(edge_kernel, cudaFuncAttributeMaxDynamicSharedMemorySize,
                         EDGE_SMEM_FLOATS * 4);
    cudaFuncSetAttribute(node_kernel, cudaFuncAttributeMaxDynamicSharedMemorySize,
                         NODE_SMEM_FLOATS * 4);
    cudaFuncSetAttribute(pq_kernel, cudaFuncAttributeMaxDynamicSharedMemorySize,
                         PQ_SMEM_FLOATS * 4);

    void *p_cnt, *p_sagg, *p_vagg;
    cudaGetSymbolAddress(&p_cnt, g_cnt);
    cudaGetSymbolAddress(&p_sagg, g_sagg);
    cudaGetSymbolAddress(&p_vagg, g_vagg);

    cudaMemcpyAsync(s, s_in, sizeof(float) * NNODE * SDIM, cudaMemcpyDeviceToDevice, 0);
    cudaMemcpyAsync(v, v_in, sizeof(float) * NNODE * 9, cudaMemcpyDeviceToDevice, 0);
    cudaMemsetAsync(p_cnt, 0, sizeof(float) * NNODE, 0);
    init_kernel<<<(NEDGE + 255) / 256, 256>>>(ei);

    const int nblk = (NNODE + 127) / 128;
    for (int l = 0; l < NLAYER; l++) {
        cudaMemsetAsync(p_sagg, 0, sizeof(float) * NNODE * SDIM, 0);
        cudaMemsetAsync(p_vagg, 0, sizeof(float) * NNODE * 9, 0);
        pq_kernel<<<nblk, NTH, PQ_SMEM_FLOATS * 4>>>(s, W1 + (size_t)l * K1DIM * HID);
        edge_kernel<<<(NEDGE + TEB - 1) / TEB, NTH, EDGE_SMEM_FLOATS * 4>>>(
            s, v, ei, dvec, r,
            W1 + (size_t)l * K1DIM * HID, b1 + (size_t)l * HID,
            W2 + (size_t)l * HID * HID,   b2 + (size_t)l * HID,
            W3 + (size_t)l * HID * M3DIM, b3 + (size_t)l * M3DIM);
        node_kernel<<<nblk, NTH, NODE_SMEM_FLOATS * 4>>>(
            s, v,
            Wn1 + (size_t)l * 2 * SDIM * HID, bn1 + (size_t)l * HID,
            Wn2 + (size_t)l * HID * SDIM,     bn2 + (size_t)l * SDIM);
    }
}